// round 12
// baseline (speedup 1.0000x reference)
#include <cuda_runtime.h>
#include <cuda_bf16.h>
#include <stdint.h>
#include <math.h>

#define NB 2
#define NS 4096
#define DM 512
#define NH 8
#define DH 64
#define MTOT (NB * NS)          // 8192
#define MK   (MTOT * DM)        // 4194304
#define NT   (NS / 64)          // 64
#define KSPLIT 4
#define NTL (NT / KSPLIT)       // 16 k-tiles per CTA
#define MFIX 12.0f              // fixed softmax max (log2 domain); scores bounded ~8

// ---------------------------------------------------------------------------
// Device-global scratch. bf16 hi/lo split pairs + fp32 split-K partials.
// ---------------------------------------------------------------------------
__device__ __align__(256) __nv_bfloat16 g_x_hi[3 * MK], g_x_lo[3 * MK];           // split q/k/v inputs
__device__ __align__(256) __nv_bfloat16 g_w_hi[4 * DM * DM], g_w_lo[4 * DM * DM]; // wT [z][n][k]
__device__ __align__(256) __nv_bfloat16 g_q_hi[MK], g_q_lo[MK];                   // [bh][s][dh], pre-scaled 0.125*log2e
__device__ __align__(256) __nv_bfloat16 g_k_hi[MK], g_k_lo[MK];                   // [bh][s][dh]
__device__ __align__(256) __nv_bfloat16 g_v_hi[MK], g_v_lo[MK];                   // [bh][s][dh]
__device__ __align__(256) __nv_bfloat16 g_a_hi[MK], g_a_lo[MK];                   // attn out [s][dm]
__device__ __align__(256) float g_po[16 * 32 * KSPLIT * 128 * 64];                // [unit][row][col] raw O partials
__device__ __align__(256) float g_pl[16 * 32 * KSPLIT * 128];                     // [unit][row] raw l partials

// ---------------------------------------------------------------------------
// PTX helpers
// ---------------------------------------------------------------------------
__device__ __forceinline__ void mma_bf16(float* c, uint32_t a0, uint32_t a1,
                                         uint32_t a2, uint32_t a3,
                                         uint32_t b0, uint32_t b1) {
    asm volatile(
        "mma.sync.aligned.m16n8k16.row.col.f32.bf16.bf16.f32 "
        "{%0,%1,%2,%3},{%4,%5,%6,%7},{%8,%9},{%0,%1,%2,%3};"
        : "+f"(c[0]), "+f"(c[1]), "+f"(c[2]), "+f"(c[3])
        : "r"(a0), "r"(a1), "r"(a2), "r"(a3), "r"(b0), "r"(b1));
}

__device__ __forceinline__ void ldm4(uint32_t* r, uint32_t addr) {
    asm volatile(
        "ldmatrix.sync.aligned.m8n8.x4.shared.b16 {%0,%1,%2,%3},[%4];"
        : "=r"(r[0]), "=r"(r[1]), "=r"(r[2]), "=r"(r[3]) : "r"(addr));
}
__device__ __forceinline__ void ldm4t(uint32_t* r, uint32_t addr) {
    asm volatile(
        "ldmatrix.sync.aligned.m8n8.x4.trans.shared.b16 {%0,%1,%2,%3},[%4];"
        : "=r"(r[0]), "=r"(r[1]), "=r"(r[2]), "=r"(r[3]) : "r"(addr));
}

__device__ __forceinline__ void cpa16(uint32_t dst, const void* src) {
    asm volatile("cp.async.cg.shared.global [%0], [%1], 16;\n" :: "r"(dst), "l"(src));
}
__device__ __forceinline__ void cp_commit() { asm volatile("cp.async.commit_group;\n"); }
__device__ __forceinline__ void cp_wait0() { asm volatile("cp.async.wait_group 0;\n"); }

__device__ __forceinline__ float ex2f(float x) {
    float y;
    asm("ex2.approx.f32 %0, %1;" : "=f"(y) : "f"(x));
    return y;
}

// 2-term bf16 split of a float pair, packed: hi = {bf16(e1)|bf16(e0)},
// lo = residuals. cvt.rn.bf16x2 keeps identical rn rounding, 6 ops total.
__device__ __forceinline__ void split_pack(float e0, float e1, uint32_t& hi, uint32_t& lo) {
    uint32_t h;
    asm("cvt.rn.bf16x2.f32 %0, %1, %2;" : "=r"(h) : "f"(e1), "f"(e0));
    float f0 = __uint_as_float(h << 16);
    float f1 = __uint_as_float(h & 0xFFFF0000u);
    float r0 = e0 - f0;
    float r1 = e1 - f1;
    asm("cvt.rn.bf16x2.f32 %0, %1, %2;" : "=r"(lo) : "f"(r1), "f"(r0));
    hi = h;
}
__device__ __forceinline__ void split1(float x, __nv_bfloat16& h, __nv_bfloat16& l) {
    h = __float2bfloat16(x);
    l = __float2bfloat16(x - __bfloat162float(h));
}

// ---------------------------------------------------------------------------
// Weight transpose + split: w[k][n] fp32 -> wT_hi/lo[n][k] bf16
// ---------------------------------------------------------------------------
__global__ void wsplit_kernel(const float* __restrict__ wq, const float* __restrict__ wk,
                              const float* __restrict__ wv, const float* __restrict__ wo) {
    __shared__ float tl[32][33];
    const float* w = blockIdx.z == 0 ? wq : blockIdx.z == 1 ? wk : blockIdx.z == 2 ? wv : wo;
    const int n0 = blockIdx.x * 32, k0 = blockIdx.y * 32;
    const int tx = threadIdx.x, ty = threadIdx.y;  // 32 x 8
#pragma unroll
    for (int i = 0; i < 32; i += 8)
        tl[ty + i][tx] = w[(size_t)(k0 + ty + i) * DM + n0 + tx];
    __syncthreads();
#pragma unroll
    for (int i = 0; i < 32; i += 8) {
        float v = tl[tx][ty + i];
        __nv_bfloat16 h, l;
        split1(v, h, l);
        size_t idx = (size_t)blockIdx.z * DM * DM + (size_t)(n0 + ty + i) * DM + k0 + tx;
        g_w_hi[idx] = h;
        g_w_lo[idx] = l;
    }
}

// ---------------------------------------------------------------------------
// Input split: q/k/v fp32 [m][k] -> g_x_hi/lo, float4-vectorized
// ---------------------------------------------------------------------------
__global__ void xsplit_kernel(const float* __restrict__ q, const float* __restrict__ k,
                              const float* __restrict__ v) {
    const int z = blockIdx.y;
    const float* src = z == 0 ? q : z == 1 ? k : v;
    int i = (blockIdx.x * 256 + threadIdx.x) * 4;
    float4 x4 = *(const float4*)(src + i);
    uint32_t h01, l01, h23, l23;
    split_pack(x4.x, x4.y, h01, l01);
    split_pack(x4.z, x4.w, h23, l23);
    uint2 hh = make_uint2(h01, h23), ll = make_uint2(l01, l23);
    *(uint2*)&g_x_hi[(size_t)z * MK + i] = hh;
    *(uint2*)&g_x_lo[(size_t)z * MK + i] = ll;
}

// ---------------------------------------------------------------------------
// bf16 3-term GEMM core: C[128x128] block, 8 warps (2m x 4n), warp 64m x 32n.
// Fragments via ldmatrix.x4. Single barrier per k-iter.
// ---------------------------------------------------------------------------
__device__ __forceinline__ void gemm_core(const __nv_bfloat16* __restrict__ aH,
                                          const __nv_bfloat16* __restrict__ aL,
                                          const __nv_bfloat16* __restrict__ wH,
                                          const __nv_bfloat16* __restrict__ wL,
                                          const float* __restrict__ bias,
                                          int mode, int z, float* __restrict__ outF) {
    extern __shared__ __align__(16) __nv_bfloat16 sb[];
    const int t = threadIdx.x, lane = t & 31, warp = t >> 5;
    const int g = lane >> 2, c4 = lane & 3;
    const int wm = warp >> 2, wn = warp & 3;
    const int m0 = blockIdx.y * 128, n0 = blockIdx.x * 128;
    const uint32_t smem_u32 = (uint32_t)__cvta_generic_to_shared(sb);

    // ldmatrix lane-dependent byte offsets (pitch 40 elems = 80 B)
    const uint32_t a_ln = (uint32_t)(((lane & 7) + ((lane >> 3) & 1) * 8) * 80 + (lane >> 4) * 16);
    const uint32_t b_ln = (uint32_t)(((lane >> 4) * 8 + (lane & 7)) * 80 + ((lane >> 3) & 1) * 16);

    const __nv_bfloat16* ptrs[4] = { aH + (size_t)m0 * DM, aL + (size_t)m0 * DM,
                                     wH + (size_t)n0 * DM, wL + (size_t)n0 * DM };

    float c[4][4][4];
#pragma unroll
    for (int a = 0; a < 4; a++)
#pragma unroll
        for (int b = 0; b < 4; b++)
#pragma unroll
            for (int e = 0; e < 4; e++) c[a][b][e] = 0.f;

    auto issue = [&](int buf, int kc0) {
#pragma unroll
        for (int arr = 0; arr < 4; arr++)
#pragma unroll
            for (int i = 0; i < 2; i++) {
                int ch = t * 2 + i;
                int row = ch >> 2, seg = ch & 3;
                const void* src = ptrs[arr] + (size_t)row * DM + kc0 + seg * 8;
                uint32_t dst = smem_u32 + ((buf * 4 + arr) * 5120 + row * 40 + seg * 8) * 2;
                cpa16(dst, src);
            }
    };

    issue(0, 0);
    cp_commit();

    for (int it = 0; it < 16; ++it) {
        cp_wait0();                      // group issued last iter complete
        __syncthreads();                 // all warps done with buf (it+1)&1
        if (it + 1 < 16) { issue((it + 1) & 1, (it + 1) * 32); cp_commit(); }

        const uint32_t Ah_u = smem_u32 + ((it & 1) * 4 + 0) * 5120 * 2;
        const uint32_t Al_u = smem_u32 + ((it & 1) * 4 + 1) * 5120 * 2;
        const uint32_t Bh_u = smem_u32 + ((it & 1) * 4 + 2) * 5120 * 2;
        const uint32_t Bl_u = smem_u32 + ((it & 1) * 4 + 3) * 5120 * 2;

#pragma unroll
        for (int ks = 0; ks < 2; ++ks) {
            uint32_t ah[4][4], al[4][4];
#pragma unroll
            for (int mt = 0; mt < 4; ++mt) {
                uint32_t ro = (uint32_t)((wm * 64 + mt * 16) * 80 + ks * 32) + a_ln;
                ldm4(ah[mt], Ah_u + ro);
                ldm4(al[mt], Al_u + ro);
            }
#pragma unroll
            for (int p = 0; p < 2; ++p) {
                uint32_t ro = (uint32_t)((wn * 32 + p * 16) * 80 + ks * 32) + b_ln;
                uint32_t bh[4], bl[4];
                ldm4(bh, Bh_u + ro);
                ldm4(bl, Bl_u + ro);
#pragma unroll
                for (int mt = 0; mt < 4; ++mt) {
                    mma_bf16(c[mt][2 * p], ah[mt][0], ah[mt][1], ah[mt][2], ah[mt][3], bh[0], bh[1]);
                    mma_bf16(c[mt][2 * p], ah[mt][0], ah[mt][1], ah[mt][2], ah[mt][3], bl[0], bl[1]);
                    mma_bf16(c[mt][2 * p], al[mt][0], al[mt][1], al[mt][2], al[mt][3], bh[0], bh[1]);
                    mma_bf16(c[mt][2 * p + 1], ah[mt][0], ah[mt][1], ah[mt][2], ah[mt][3], bh[2], bh[3]);
                    mma_bf16(c[mt][2 * p + 1], ah[mt][0], ah[mt][1], ah[mt][2], ah[mt][3], bl[2], bl[3]);
                    mma_bf16(c[mt][2 * p + 1], al[mt][0], al[mt][1], al[mt][2], al[mt][3], bh[2], bh[3]);
                }
            }
        }
    }

    // epilogue
    __nv_bfloat16* dh = z == 0 ? g_q_hi : z == 1 ? g_k_hi : g_v_hi;
    __nv_bfloat16* dl = z == 0 ? g_q_lo : z == 1 ? g_k_lo : g_v_lo;
    const float qscale = 0.125f * 1.44269504f;   // 1/sqrt(dh) * log2(e)
#pragma unroll
    for (int mt = 0; mt < 4; ++mt) {
        int mA = m0 + wm * 64 + mt * 16 + g;
#pragma unroll
        for (int nt = 0; nt < 4; ++nt) {
            int n = n0 + wn * 32 + nt * 8 + c4 * 2;
            float b0 = bias[n], b1 = bias[n + 1];
            float v00 = c[mt][nt][0] + b0, v01 = c[mt][nt][1] + b1;
            float v10 = c[mt][nt][2] + b0, v11 = c[mt][nt][3] + b1;
            if (mode == 0) {
                if (z == 0) { v00 *= qscale; v01 *= qscale; v10 *= qscale; v11 *= qscale; }
                int b_ = mA >> 12, s_ = mA & (NS - 1), h_ = n >> 6, d_ = n & 63;
                size_t idx = ((size_t)(b_ * NH + h_) * NS + s_) * DH + d_;
                uint32_t hi, lo;
                split_pack(v00, v01, hi, lo);
                *(uint32_t*)&dh[idx] = hi;
                *(uint32_t*)&dl[idx] = lo;
                split_pack(v10, v11, hi, lo);
                *(uint32_t*)&dh[idx + 8 * DH] = hi;
                *(uint32_t*)&dl[idx + 8 * DH] = lo;
            } else {
                outF[(size_t)mA * DM + n] = v00;
                outF[(size_t)mA * DM + n + 1] = v01;
                outF[(size_t)(mA + 8) * DM + n] = v10;
                outF[(size_t)(mA + 8) * DM + n + 1] = v11;
            }
        }
    }
}

__global__ __launch_bounds__(256, 2) void gemm_qkv_kernel(const float* __restrict__ bq,
                                                          const float* __restrict__ bk,
                                                          const float* __restrict__ bv) {
    const int z = blockIdx.z;
    const float* bias = z == 0 ? bq : z == 1 ? bk : bv;
    gemm_core(g_x_hi + (size_t)z * MK, g_x_lo + (size_t)z * MK,
              g_w_hi + (size_t)z * DM * DM, g_w_lo + (size_t)z * DM * DM,
              bias, 0, z, nullptr);
}

__global__ __launch_bounds__(256, 2) void gemm_out_kernel(const float* __restrict__ bo,
                                                          float* __restrict__ out) {
    gemm_core(g_a_hi, g_a_lo, g_w_hi + (size_t)3 * DM * DM, g_w_lo + (size_t)3 * DM * DM,
              bo, 1, 0, out);
}

// ---------------------------------------------------------------------------
// Flash attention, bf16 3-term mma, FIXED-MAX softmax, SPLIT-K (KSPLIT=4),
// 128 THREADS / 4 WARPS: each warp owns 32 q-rows (2 m-tiles of 16), so every
// K/V fragment load feeds 12 mmas instead of 6 -- per-SM LDSM traffic drops
// from 590KB to 327KB per k-tile, putting the tensor pipe (not the smem port)
// on the critical path. 2 CTAs/SM, independent CTAs overlap phases.
// smem: 2 bufs x {Kh,Kl,Vh,Vl} x 64x72 (73728 B) + Q hi/lo 128x72 (36864 B)
// = 110592 B.
// ---------------------------------------------------------------------------
__global__ __launch_bounds__(128, 2) void attn_kernel() {
    extern __shared__ __align__(16) __nv_bfloat16 sb[];
    const int t = threadIdx.x, lane = t & 31, warp = t >> 5;   // 4 warps
    const int g = lane >> 2, c4 = lane & 3;
    const int bh = blockIdx.y;
    const int kh = blockIdx.z;
    const int qr0 = blockIdx.x * 128;
    const int qloc = warp * 32;                 // 32 rows per warp (2 m-tiles)
    const int unit = (bh * 32 + blockIdx.x) * KSPLIT + kh;
    const int kt0 = kh * NTL;
    const uint32_t smem_u32 = (uint32_t)__cvta_generic_to_shared(sb);
    const size_t bho = (size_t)bh * NS * DH;

    const uint32_t qh_u = smem_u32 + (8 * 4608) * 2;
    const uint32_t ql_u = qh_u + 128 * 72 * 2;

    // ldmatrix lane-dependent byte offsets (pitch 72 elems = 144 B)
    const uint32_t a_ln = (uint32_t)(((lane & 7) + ((lane >> 3) & 1) * 8) * 144 + (lane >> 4) * 16);
    const uint32_t b_ln = (uint32_t)(((lane >> 4) * 8 + (lane & 7)) * 144 + ((lane >> 3) & 1) * 16);

    const __nv_bfloat16* srcs[4] = { g_k_hi + bho, g_k_lo + bho, g_v_hi + bho, g_v_lo + bho };

    auto issue = [&](int buf, int kt) {
        const int k0 = kt * 64;
#pragma unroll
        for (int arr = 0; arr < 4; arr++)
#pragma unroll
            for (int i = 0; i < 4; i++) {
                int ch = t * 4 + i;              // 0..511
                int row = ch >> 3, seg = ch & 7;
                const void* src = srcs[arr] + (size_t)(k0 + row) * DH + seg * 8;
                uint32_t dst = smem_u32 + ((buf * 4 + arr) * 4608 + row * 72 + seg * 8) * 2;
                cpa16(dst, src);
            }
    };

    // prologue: Q tile + KV(kt0) as group 0 (128 threads -> 8 chunks/thread/array)
    {
#pragma unroll
        for (int i = 0; i < 8; i++) {
            int ch = t * 8 + i;                  // 0..1023
            int row = ch >> 3, seg = ch & 7;
            cpa16(qh_u + (row * 72 + seg * 8) * 2, g_q_hi + bho + (size_t)(qr0 + row) * DH + seg * 8);
            cpa16(ql_u + (row * 72 + seg * 8) * 2, g_q_lo + bho + (size_t)(qr0 + row) * DH + seg * 8);
        }
    }
    issue(0, kt0);
    cp_commit();

    float o0[8][4], o1[8][4];
#pragma unroll
    for (int i = 0; i < 8; i++)
#pragma unroll
        for (int e = 0; e < 4; e++) { o0[i][e] = 0.f; o1[i][e] = 0.f; }
    float l00 = 0.f, l01 = 0.f, l10 = 0.f, l11 = 0.f;

    for (int lkt = 0; lkt < NTL; ++lkt) {
        cp_wait0();                      // group issued last iter complete
        __syncthreads();                 // all warps done reading buf (lkt+1)&1

        const int bb = lkt & 1;
        const uint32_t kh_u = smem_u32 + ((bb * 4 + 0) * 4608) * 2;
        const uint32_t kl_u = smem_u32 + ((bb * 4 + 1) * 4608) * 2;
        const uint32_t vh_u = smem_u32 + ((bb * 4 + 2) * 4608) * 2;
        const uint32_t vl_u = smem_u32 + ((bb * 4 + 3) * 4608) * 2;

        // ---- S = Q K^T - MFIX for both m-tiles (accumulators pre-loaded)
        float s0[8][4], s1[8][4];
#pragma unroll
        for (int i = 0; i < 8; i++)
#pragma unroll
            for (int e = 0; e < 4; e++) { s0[i][e] = -MFIX; s1[i][e] = -MFIX; }

#pragma unroll
        for (int ks = 0; ks < 4; ++ks) {
            uint32_t a0h[4], a0l[4], a1h[4], a1l[4];
            uint32_t aro0 = (uint32_t)(qloc * 144 + ks * 32) + a_ln;
            uint32_t aro1 = (uint32_t)((qloc + 16) * 144 + ks * 32) + a_ln;
            ldm4(a0h, qh_u + aro0);
            ldm4(a0l, ql_u + aro0);
            ldm4(a1h, qh_u + aro1);
            ldm4(a1l, ql_u + aro1);
#pragma unroll
            for (int p = 0; p < 4; ++p) {
                uint32_t bro = (uint32_t)(p * 16 * 144 + ks * 32) + b_ln;
                uint32_t bhr[4], blr[4];
                ldm4(bhr, kh_u + bro);
                ldm4(blr, kl_u + bro);
                mma_bf16(s0[2 * p],     a0h[0], a0h[1], a0h[2], a0h[3], bhr[0], bhr[1]);
                mma_bf16(s0[2 * p],     a0h[0], a0h[1], a0h[2], a0h[3], blr[0], blr[1]);
                mma_bf16(s0[2 * p],     a0l[0], a0l[1], a0l[2], a0l[3], bhr[0], bhr[1]);
                mma_bf16(s0[2 * p + 1], a0h[0], a0h[1], a0h[2], a0h[3], bhr[2], bhr[3]);
                mma_bf16(s0[2 * p + 1], a0h[0], a0h[1], a0h[2], a0h[3], blr[2], blr[3]);
                mma_bf16(s0[2 * p + 1], a0l[0], a0l[1], a0l[2], a0l[3], bhr[2], bhr[3]);
                mma_bf16(s1[2 * p],     a1h[0], a1h[1], a1h[2], a1h[3], bhr[0], bhr[1]);
                mma_bf16(s1[2 * p],     a1h[0], a1h[1], a1h[2], a1h[3], blr[0], blr[1]);
                mma_bf16(s1[2 * p],     a1l[0], a1l[1], a1l[2], a1l[3], bhr[0], bhr[1]);
                mma_bf16(s1[2 * p + 1], a1h[0], a1h[1], a1h[2], a1h[3], bhr[2], bhr[3]);
                mma_bf16(s1[2 * p + 1], a1h[0], a1h[1], a1h[2], a1h[3], blr[2], blr[3]);
                mma_bf16(s1[2 * p + 1], a1l[0], a1l[1], a1l[2], a1l[3], bhr[2], bhr[3]);
            }
        }

        // ---- prefetch tile lkt+1 (after S issue; hazard covered by barrier)
        if (lkt + 1 < NTL) { issue((lkt + 1) & 1, kt0 + lkt + 1); cp_commit(); }

        // ---- phase a: MUFU/ALU burst -- exp + l accumulate + splits (both mts)
        uint32_t ph0[16], pl0[16], ph1[16], pl1[16];
#pragma unroll
        for (int tk = 0; tk < 4; ++tk) {
            float p00 = ex2f(s0[2 * tk][0]);
            float p01 = ex2f(s0[2 * tk][1]);
            float p02 = ex2f(s0[2 * tk][2]);
            float p03 = ex2f(s0[2 * tk][3]);
            float p10 = ex2f(s0[2 * tk + 1][0]);
            float p11 = ex2f(s0[2 * tk + 1][1]);
            float p12 = ex2f(s0[2 * tk + 1][2]);
            float p13 = ex2f(s0[2 * tk + 1][3]);
            l00 += p00 + p01 + p10 + p11;
            l01 += p02 + p03 + p12 + p13;
            split_pack(p00, p01, ph0[tk * 4 + 0], pl0[tk * 4 + 0]);
            split_pack(p02, p03, ph0[tk * 4 + 1], pl0[tk * 4 + 1]);
            split_pack(p10, p11, ph0[tk * 4 + 2], pl0[tk * 4 + 2]);
            split_pack(p12, p13, ph0[tk * 4 + 3], pl0[tk * 4 + 3]);
            float q00 = ex2f(s1[2 * tk][0]);
            float q01 = ex2f(s1[2 * tk][1]);
            float q02 = ex2f(s1[2 * tk][2]);
            float q03 = ex2f(s1[2 * tk][3]);
            float q10 = ex2f(s1[2 * tk + 1][0]);
            float q11 = ex2f(s1[2 * tk + 1][1]);
            float q12 = ex2f(s1[2 * tk + 1][2]);
            float q13 = ex2f(s1[2 * tk + 1][3]);
            l10 += q00 + q01 + q10 + q11;
            l11 += q02 + q03 + q12 + q13;
            split_pack(q00, q01, ph1[tk * 4 + 0], pl1[tk * 4 + 0]);
            split_pack(q02, q03, ph1[tk * 4 + 1], pl1[tk * 4 + 1]);
            split_pack(q10, q11, ph1[tk * 4 + 2], pl1[tk * 4 + 2]);
            split_pack(q12, q13, ph1[tk * 4 + 3], pl1[tk * 4 + 3]);
        }

        // ---- phase b: uninterrupted ldmatrix + mma burst (PV, both m-tiles
        //      share each V fragment load)
        {
            int jbase = (lane & 15);
            int coff = (lane >> 4) * 8;
#pragma unroll
            for (int tk = 0; tk < 4; ++tk) {
                int jrow = tk * 16 + jbase;
#pragma unroll
                for (int np = 0; np < 4; ++np) {
                    uint32_t vh[4], vl[4];
                    ldm4t(vh, vh_u + (jrow * 72 + np * 16 + coff) * 2);
                    ldm4t(vl, vl_u + (jrow * 72 + np * 16 + coff) * 2);
                    mma_bf16(o0[np * 2],     ph0[tk*4+0], ph0[tk*4+1], ph0[tk*4+2], ph0[tk*4+3], vh[0], vh[1]);
                    mma_bf16(o0[np * 2],     ph0[tk*4+0], ph0[tk*4+1], ph0[tk*4+2], ph0[tk*4+3], vl[0], vl[1]);
                    mma_bf16(o0[np * 2],     pl0[tk*4+0], pl0[tk*4+1], pl0[tk*4+2], pl0[tk*4+3], vh[0], vh[1]);
                    mma_bf16(o0[np * 2 + 1], ph0[tk*4+0], ph0[tk*4+1], ph0[tk*4+2], ph0[tk*4+3], vh[2], vh[3]);
                    mma_bf16(o0[np * 2 + 1], ph0[tk*4+0], ph0[tk*4+1], ph0[tk*4+2], ph0[tk*4+3], vl[2], vl[3]);
                    mma_bf16(o0[np * 2 + 1], pl0[tk*4+0], pl0[tk*4+1], pl0[tk*4+2], pl0[tk*4+3], vh[2], vh[3]);
                    mma_bf16(o1[np * 2],     ph1[tk*4+0], ph1[tk*4+1], ph1[tk*4+2], ph1[tk*4+3], vh[0], vh[1]);
                    mma_bf16(o1[np * 2],     ph1[tk*4+0], ph1[tk*4+1], ph1[tk*4+2], ph1[tk*4+3], vl[0], vl[1]);
                    mma_bf16(o1[np * 2],     pl1[tk*4+0], pl1[tk*4+1], pl1[tk*4+2], pl1[tk*4+3], vh[0], vh[1]);
                    mma_bf16(o1[np * 2 + 1], ph1[tk*4+0], ph1[tk*4+1], ph1[tk*4+2], ph1[tk*4+3], vh[2], vh[3]);
                    mma_bf16(o1[np * 2 + 1], ph1[tk*4+0], ph1[tk*4+1], ph1[tk*4+2], ph1[tk*4+3], vl[2], vl[3]);
                    mma_bf16(o1[np * 2 + 1], pl1[tk*4+0], pl1[tk*4+1], pl1[tk*4+2], pl1[tk*4+3], vh[2], vh[3]);
                }
            }
        }
    }

    // one-time l reduction across the 4 lanes of each row quad
    l00 += __shfl_xor_sync(0xffffffffu, l00, 1);
    l00 += __shfl_xor_sync(0xffffffffu, l00, 2);
    l01 += __shfl_xor_sync(0xffffffffu, l01, 1);
    l01 += __shfl_xor_sync(0xffffffffu, l01, 2);
    l10 += __shfl_xor_sync(0xffffffffu, l10, 1);
    l10 += __shfl_xor_sync(0xffffffffu, l10, 2);
    l11 += __shfl_xor_sync(0xffffffffu, l11, 1);
    l11 += __shfl_xor_sync(0xffffffffu, l11, 2);

    // epilogue: write RAW fp32 partials (no normalization), both m-tiles
    {
        int r0 = qloc + g, r1 = qloc + g + 8;
        int r2 = qloc + 16 + g, r3 = qloc + 16 + g + 8;
        if (c4 == 0) {
            g_pl[(size_t)unit * 128 + r0] = l00;
            g_pl[(size_t)unit * 128 + r1] = l01;
            g_pl[(size_t)unit * 128 + r2] = l10;
            g_pl[(size_t)unit * 128 + r3] = l11;
        }
        float* base0 = g_po + ((size_t)unit * 128 + r0) * 64;
        float* base1 = g_po + ((size_t)unit * 128 + r1) * 64;
        float* base2 = g_po + ((size_t)unit * 128 + r2) * 64;
        float* base3 = g_po + ((size_t)unit * 128 + r3) * 64;
#pragma unroll
        for (int nt = 0; nt < 8; ++nt) {
            int d = nt * 8 + c4 * 2;
            *(float2*)&base0[d] = make_float2(o0[nt][0], o0[nt][1]);
            *(float2*)&base1[d] = make_float2(o0[nt][2], o0[nt][3]);
            *(float2*)&base2[d] = make_float2(o1[nt][0], o1[nt][1]);
            *(float2*)&base3[d] = make_float2(o1[nt][2], o1[nt][3]);
        }
    }
}

// ---------------------------------------------------------------------------
// Combine split-K partials: O = (sum O_k) / (sum l_k), then bf16 hi/lo split
// into g_a_hi/lo [s][dm]. Block per (qt, bh); 256 threads; thread = (row%4, col).
// ---------------------------------------------------------------------------
__global__ __launch_bounds__(256) void combine_kernel() {
    const int qt = blockIdx.x, bh = blockIdx.y;
    const int ua = (bh * 32 + qt) * KSPLIT;
    const int t = threadIdx.x;
    const int col = t & 63, rbase = t >> 6;      // 4 rows per pass
    const int b_ = bh >> 3, h_ = bh & 7;
#pragma unroll 4
    for (int i = 0; i < 32; i++) {
        int row = rbase + i * 4;
        float lsum = 0.f, osum = 0.f;
#pragma unroll
        for (int u = 0; u < KSPLIT; u++) {
            lsum += g_pl[(size_t)(ua + u) * 128 + row];
            osum += g_po[((size_t)(ua + u) * 128 + row) * 64 + col];
        }
        float v = osum / lsum;
        __nv_bfloat16 h, l;
        split1(v, h, l);
        size_t idx = ((size_t)(b_ * NS + qt * 128 + row)) * DM + h_ * 64 + col;
        g_a_hi[idx] = h;
        g_a_lo[idx] = l;
    }
}

// ---------------------------------------------------------------------------
extern "C" void kernel_launch(void* const* d_in, const int* in_sizes, int n_in,
                              void* d_out, int out_size) {
    const float* q  = (const float*)d_in[0];
    const float* k  = (const float*)d_in[1];
    const float* v  = (const float*)d_in[2];
    const float* wq = (const float*)d_in[3];
    const float* bq = (const float*)d_in[4];
    const float* wk = (const float*)d_in[5];
    const float* bk = (const float*)d_in[6];
    const float* wv = (const float*)d_in[7];
    const float* bv = (const float*)d_in[8];
    const float* wo = (const float*)d_in[9];
    const float* bo = (const float*)d_in[10];
    float* out = (float*)d_out;

    const int smem_gemm = 2 * 4 * 128 * 40 * 2;                  // 81920
    const int smem_attn = (8 * 4608 + 2 * 128 * 72) * 2;         // 110592
    cudaFuncSetAttribute(gemm_qkv_kernel, cudaFuncAttributeMaxDynamicSharedMemorySize, smem_gemm);
    cudaFuncSetAttribute(gemm_out_kernel, cudaFuncAttributeMaxDynamicSharedMemorySize, smem_gemm);
    cudaFuncSetAttribute(attn_kernel,     cudaFuncAttributeMaxDynamicSharedMemorySize, smem_attn);

    wsplit_kernel<<<dim3(16, 16, 4), dim3(32, 8)>>>(wq, wk, wv, wo);
    xsplit_kernel<<<dim3(MK / 1024, 3), 256>>>(q, k, v);
    gemm_qkv_kernel<<<dim3(4, 64, 3), 256, smem_gemm>>>(bq, bk, bv);
    attn_kernel<<<dim3(32, 16, KSPLIT), 128, smem_attn>>>();
    combine_kernel<<<dim3(32, 16), 256>>>();
    gemm_out_kernel<<<dim3(4, 64), 256, smem_gemm>>>(bo, out);
}

// round 13
// speedup vs baseline: 1.1117x; 1.1117x over previous
#include <cuda_runtime.h>
#include <cuda_bf16.h>
#include <stdint.h>
#include <math.h>

#define NB 2
#define NS 4096
#define DM 512
#define NH 8
#define DH 64
#define MTOT (NB * NS)          // 8192
#define MK   (MTOT * DM)        // 4194304
#define NT   (NS / 64)          // 64
#define KSPLIT 4
#define NTL (NT / KSPLIT)       // 16 k-tiles per CTA
#define MFIX 12.0f              // fixed softmax max (log2 domain); scores bounded ~8

// ---------------------------------------------------------------------------
// Device-global scratch. bf16 hi/lo split pairs + fp32 split-K partials.
// ---------------------------------------------------------------------------
__device__ __align__(256) __nv_bfloat16 g_w_hi[4 * DM * DM], g_w_lo[4 * DM * DM]; // wT [z][n][k]
__device__ __align__(256) __nv_bfloat16 g_q_hi[MK], g_q_lo[MK];                   // [bh][s][dh], pre-scaled 0.125*log2e
__device__ __align__(256) __nv_bfloat16 g_k_hi[MK], g_k_lo[MK];                   // [bh][s][dh]
__device__ __align__(256) __nv_bfloat16 g_v_hi[MK], g_v_lo[MK];                   // [bh][s][dh]
__device__ __align__(256) __nv_bfloat16 g_a_hi[MK], g_a_lo[MK];                   // attn out [s][dm]
__device__ __align__(256) float g_po[16 * 32 * KSPLIT * 128 * 64];                // [unit][row][col] raw O partials
__device__ __align__(256) float g_pl[16 * 32 * KSPLIT * 128];                     // [unit][row] raw l partials

// ---------------------------------------------------------------------------
// PTX helpers
// ---------------------------------------------------------------------------
__device__ __forceinline__ void mma_bf16(float* c, uint32_t a0, uint32_t a1,
                                         uint32_t a2, uint32_t a3,
                                         uint32_t b0, uint32_t b1) {
    asm volatile(
        "mma.sync.aligned.m16n8k16.row.col.f32.bf16.bf16.f32 "
        "{%0,%1,%2,%3},{%4,%5,%6,%7},{%8,%9},{%0,%1,%2,%3};"
        : "+f"(c[0]), "+f"(c[1]), "+f"(c[2]), "+f"(c[3])
        : "r"(a0), "r"(a1), "r"(a2), "r"(a3), "r"(b0), "r"(b1));
}

__device__ __forceinline__ void ldm4(uint32_t* r, uint32_t addr) {
    asm volatile(
        "ldmatrix.sync.aligned.m8n8.x4.shared.b16 {%0,%1,%2,%3},[%4];"
        : "=r"(r[0]), "=r"(r[1]), "=r"(r[2]), "=r"(r[3]) : "r"(addr));
}
__device__ __forceinline__ void ldm4t(uint32_t* r, uint32_t addr) {
    asm volatile(
        "ldmatrix.sync.aligned.m8n8.x4.trans.shared.b16 {%0,%1,%2,%3},[%4];"
        : "=r"(r[0]), "=r"(r[1]), "=r"(r[2]), "=r"(r[3]) : "r"(addr));
}

__device__ __forceinline__ void cpa16(uint32_t dst, const void* src) {
    asm volatile("cp.async.cg.shared.global [%0], [%1], 16;\n" :: "r"(dst), "l"(src));
}
__device__ __forceinline__ void cp_commit() { asm volatile("cp.async.commit_group;\n"); }
__device__ __forceinline__ void cp_wait0() { asm volatile("cp.async.wait_group 0;\n"); }

__device__ __forceinline__ float ex2f(float x) {
    float y;
    asm("ex2.approx.f32 %0, %1;" : "=f"(y) : "f"(x));
    return y;
}

// 2-term bf16 split of a float pair, packed: hi = {bf16(e1)|bf16(e0)},
// lo = residuals. cvt.rn.bf16x2 keeps identical rn rounding, 6 ops total.
__device__ __forceinline__ void split_pack(float e0, float e1, uint32_t& hi, uint32_t& lo) {
    uint32_t h;
    asm("cvt.rn.bf16x2.f32 %0, %1, %2;" : "=r"(h) : "f"(e1), "f"(e0));
    float f0 = __uint_as_float(h << 16);
    float f1 = __uint_as_float(h & 0xFFFF0000u);
    float r0 = e0 - f0;
    float r1 = e1 - f1;
    asm("cvt.rn.bf16x2.f32 %0, %1, %2;" : "=r"(lo) : "f"(r1), "f"(r0));
    hi = h;
}
__device__ __forceinline__ void split1(float x, __nv_bfloat16& h, __nv_bfloat16& l) {
    h = __float2bfloat16(x);
    l = __float2bfloat16(x - __bfloat162float(h));
}

// ---------------------------------------------------------------------------
// Weight transpose + split: w[k][n] fp32 -> wT_hi/lo[n][k] bf16
// ---------------------------------------------------------------------------
__global__ void wsplit_kernel(const float* __restrict__ wq, const float* __restrict__ wk,
                              const float* __restrict__ wv, const float* __restrict__ wo) {
    __shared__ float tl[32][33];
    const float* w = blockIdx.z == 0 ? wq : blockIdx.z == 1 ? wk : blockIdx.z == 2 ? wv : wo;
    const int n0 = blockIdx.x * 32, k0 = blockIdx.y * 32;
    const int tx = threadIdx.x, ty = threadIdx.y;  // 32 x 8
#pragma unroll
    for (int i = 0; i < 32; i += 8)
        tl[ty + i][tx] = w[(size_t)(k0 + ty + i) * DM + n0 + tx];
    __syncthreads();
#pragma unroll
    for (int i = 0; i < 32; i += 8) {
        float v = tl[tx][ty + i];
        __nv_bfloat16 h, l;
        split1(v, h, l);
        size_t idx = (size_t)blockIdx.z * DM * DM + (size_t)(n0 + ty + i) * DM + k0 + tx;
        g_w_hi[idx] = h;
        g_w_lo[idx] = l;
    }
}

// ---------------------------------------------------------------------------
// bf16 3-term GEMM core: C[128x128] block, 8 warps (2m x 4n), warp 64m x 32n.
// Fragments via ldmatrix.x4. Single barrier per k-iter.
// AFP32=1: A read as raw fp32 (LDG float4 -> split_pack -> STS), one iteration
// ahead, replacing the xsplit pre-pass with zero extra gmem traffic.
// AFP32=0: A read as bf16 hi/lo via cp.async (gemm_out path).
// ---------------------------------------------------------------------------
template <int AFP32>
__device__ __forceinline__ void gemm_core(const float* __restrict__ aF,
                                          const __nv_bfloat16* __restrict__ aH,
                                          const __nv_bfloat16* __restrict__ aL,
                                          const __nv_bfloat16* __restrict__ wH,
                                          const __nv_bfloat16* __restrict__ wL,
                                          const float* __restrict__ bias,
                                          int mode, int z, float* __restrict__ outF) {
    extern __shared__ __align__(16) __nv_bfloat16 sb[];
    const int t = threadIdx.x, lane = t & 31, warp = t >> 5;
    const int g = lane >> 2, c4 = lane & 3;
    const int wm = warp >> 2, wn = warp & 3;
    const int m0 = blockIdx.y * 128, n0 = blockIdx.x * 128;
    const uint32_t smem_u32 = (uint32_t)__cvta_generic_to_shared(sb);

    // ldmatrix lane-dependent byte offsets (pitch 40 elems = 80 B)
    const uint32_t a_ln = (uint32_t)(((lane & 7) + ((lane >> 3) & 1) * 8) * 80 + (lane >> 4) * 16);
    const uint32_t b_ln = (uint32_t)(((lane >> 4) * 8 + (lane & 7)) * 80 + ((lane >> 3) & 1) * 16);

    float c[4][4][4];
#pragma unroll
    for (int a = 0; a < 4; a++)
#pragma unroll
        for (int b = 0; b < 4; b++)
#pragma unroll
            for (int e = 0; e < 4; e++) c[a][b][e] = 0.f;

    // B (weights): always cp.async into arrays 2,3
    auto issueB = [&](int buf, int kc0) {
#pragma unroll
        for (int arr = 2; arr < 4; arr++)
#pragma unroll
            for (int i = 0; i < 2; i++) {
                int ch = t * 2 + i;
                int row = ch >> 2, seg = ch & 3;
                const __nv_bfloat16* base = (arr == 2) ? wH : wL;
                const void* src = base + (size_t)(n0 + row) * DM + kc0 + seg * 8;
                uint32_t dst = smem_u32 + ((buf * 4 + arr) * 5120 + row * 40 + seg * 8) * 2;
                cpa16(dst, src);
            }
    };
    // A via cp.async (AFP32=0)
    auto issueA = [&](int buf, int kc0) {
#pragma unroll
        for (int arr = 0; arr < 2; arr++)
#pragma unroll
            for (int i = 0; i < 2; i++) {
                int ch = t * 2 + i;
                int row = ch >> 2, seg = ch & 3;
                const __nv_bfloat16* base = (arr == 0) ? aH : aL;
                const void* src = base + (size_t)(m0 + row) * DM + kc0 + seg * 8;
                uint32_t dst = smem_u32 + ((buf * 4 + arr) * 5120 + row * 40 + seg * 8) * 2;
                cpa16(dst, src);
            }
    };

    // A via fp32 LDG + split + STS (AFP32=1); ar holds one 128x32 tile slice
    float4 ar[4];
    auto ldgA = [&](int kc0) {
#pragma unroll
        for (int i = 0; i < 2; i++) {
            int ch = t * 2 + i;
            int row = ch >> 2, seg = ch & 3;
            const float* p = aF + (size_t)(m0 + row) * DM + kc0 + seg * 8;
            ar[2 * i]     = *(const float4*)p;
            ar[2 * i + 1] = *(const float4*)(p + 4);
        }
    };
    auto stsA = [&](int buf) {
#pragma unroll
        for (int i = 0; i < 2; i++) {
            int ch = t * 2 + i;
            int row = ch >> 2, seg = ch & 3;
            uint32_t h0, l0, h1, l1, h2, l2, h3, l3;
            split_pack(ar[2 * i].x, ar[2 * i].y, h0, l0);
            split_pack(ar[2 * i].z, ar[2 * i].w, h1, l1);
            split_pack(ar[2 * i + 1].x, ar[2 * i + 1].y, h2, l2);
            split_pack(ar[2 * i + 1].z, ar[2 * i + 1].w, h3, l3);
            uint32_t off_h = ((buf * 4 + 0) * 5120 + row * 40 + seg * 8) * 2;
            uint32_t off_l = ((buf * 4 + 1) * 5120 + row * 40 + seg * 8) * 2;
            *reinterpret_cast<uint4*>(reinterpret_cast<char*>(sb) + off_h) = make_uint4(h0, h1, h2, h3);
            *reinterpret_cast<uint4*>(reinterpret_cast<char*>(sb) + off_l) = make_uint4(l0, l1, l2, l3);
        }
    };

    if (AFP32) {
        ldgA(0);
        stsA(0);
        issueB(0, 0);
        cp_commit();
        ldgA(32);                        // stash A(1) in regs through iter 0
    } else {
        issueA(0, 0);
        issueB(0, 0);
        cp_commit();
    }

    for (int it = 0; it < 16; ++it) {
        cp_wait0();                      // group issued last iter complete
        __syncthreads();                 // all warps done with buf (it+1)&1
        if (it + 1 < 16) {
            if (AFP32) {
                stsA((it + 1) & 1);      // ar holds A(it+1); buf freed by barrier
                issueB((it + 1) & 1, (it + 1) * 32);
                cp_commit();
                if (it + 2 < 16) ldgA((it + 2) * 32);
            } else {
                issueA((it + 1) & 1, (it + 1) * 32);
                issueB((it + 1) & 1, (it + 1) * 32);
                cp_commit();
            }
        }

        const uint32_t Ah_u = smem_u32 + ((it & 1) * 4 + 0) * 5120 * 2;
        const uint32_t Al_u = smem_u32 + ((it & 1) * 4 + 1) * 5120 * 2;
        const uint32_t Bh_u = smem_u32 + ((it & 1) * 4 + 2) * 5120 * 2;
        const uint32_t Bl_u = smem_u32 + ((it & 1) * 4 + 3) * 5120 * 2;

#pragma unroll
        for (int ks = 0; ks < 2; ++ks) {
            uint32_t ah[4][4], al[4][4];
#pragma unroll
            for (int mt = 0; mt < 4; ++mt) {
                uint32_t ro = (uint32_t)((wm * 64 + mt * 16) * 80 + ks * 32) + a_ln;
                ldm4(ah[mt], Ah_u + ro);
                ldm4(al[mt], Al_u + ro);
            }
#pragma unroll
            for (int p = 0; p < 2; ++p) {
                uint32_t ro = (uint32_t)((wn * 32 + p * 16) * 80 + ks * 32) + b_ln;
                uint32_t bh[4], bl[4];
                ldm4(bh, Bh_u + ro);
                ldm4(bl, Bl_u + ro);
#pragma unroll
                for (int mt = 0; mt < 4; ++mt) {
                    mma_bf16(c[mt][2 * p], ah[mt][0], ah[mt][1], ah[mt][2], ah[mt][3], bh[0], bh[1]);
                    mma_bf16(c[mt][2 * p], ah[mt][0], ah[mt][1], ah[mt][2], ah[mt][3], bl[0], bl[1]);
                    mma_bf16(c[mt][2 * p], al[mt][0], al[mt][1], al[mt][2], al[mt][3], bh[0], bh[1]);
                    mma_bf16(c[mt][2 * p + 1], ah[mt][0], ah[mt][1], ah[mt][2], ah[mt][3], bh[2], bh[3]);
                    mma_bf16(c[mt][2 * p + 1], ah[mt][0], ah[mt][1], ah[mt][2], ah[mt][3], bl[2], bl[3]);
                    mma_bf16(c[mt][2 * p + 1], al[mt][0], al[mt][1], al[mt][2], al[mt][3], bh[2], bh[3]);
                }
            }
        }
    }

    // epilogue
    __nv_bfloat16* dh = z == 0 ? g_q_hi : z == 1 ? g_k_hi : g_v_hi;
    __nv_bfloat16* dl = z == 0 ? g_q_lo : z == 1 ? g_k_lo : g_v_lo;
    const float qscale = 0.125f * 1.44269504f;   // 1/sqrt(dh) * log2(e)
#pragma unroll
    for (int mt = 0; mt < 4; ++mt) {
        int mA = m0 + wm * 64 + mt * 16 + g;
#pragma unroll
        for (int nt = 0; nt < 4; ++nt) {
            int n = n0 + wn * 32 + nt * 8 + c4 * 2;
            float b0 = bias[n], b1 = bias[n + 1];
            float v00 = c[mt][nt][0] + b0, v01 = c[mt][nt][1] + b1;
            float v10 = c[mt][nt][2] + b0, v11 = c[mt][nt][3] + b1;
            if (mode == 0) {
                if (z == 0) { v00 *= qscale; v01 *= qscale; v10 *= qscale; v11 *= qscale; }
                int b_ = mA >> 12, s_ = mA & (NS - 1), h_ = n >> 6, d_ = n & 63;
                size_t idx = ((size_t)(b_ * NH + h_) * NS + s_) * DH + d_;
                uint32_t hi, lo;
                split_pack(v00, v01, hi, lo);
                *(uint32_t*)&dh[idx] = hi;
                *(uint32_t*)&dl[idx] = lo;
                split_pack(v10, v11, hi, lo);
                *(uint32_t*)&dh[idx + 8 * DH] = hi;
                *(uint32_t*)&dl[idx + 8 * DH] = lo;
            } else {
                outF[(size_t)mA * DM + n] = v00;
                outF[(size_t)mA * DM + n + 1] = v01;
                outF[(size_t)(mA + 8) * DM + n] = v10;
                outF[(size_t)(mA + 8) * DM + n + 1] = v11;
            }
        }
    }
}

__global__ __launch_bounds__(256, 2) void gemm_qkv_kernel(const float* __restrict__ q,
                                                          const float* __restrict__ k,
                                                          const float* __restrict__ v,
                                                          const float* __restrict__ bq,
                                                          const float* __restrict__ bk,
                                                          const float* __restrict__ bv) {
    const int z = blockIdx.z;
    const float* aF = z == 0 ? q : z == 1 ? k : v;
    const float* bias = z == 0 ? bq : z == 1 ? bk : bv;
    gemm_core<1>(aF, nullptr, nullptr,
                 g_w_hi + (size_t)z * DM * DM, g_w_lo + (size_t)z * DM * DM,
                 bias, 0, z, nullptr);
}

__global__ __launch_bounds__(256, 2) void gemm_out_kernel(const float* __restrict__ bo,
                                                          float* __restrict__ out) {
    gemm_core<0>(nullptr, g_a_hi, g_a_lo,
                 g_w_hi + (size_t)3 * DM * DM, g_w_lo + (size_t)3 * DM * DM,
                 bo, 1, 0, out);
}

// ---------------------------------------------------------------------------
// Flash attention (R11 config, best measured): bf16 3-term mma, FIXED-MAX
// softmax, SPLIT-K (KSPLIT=4), 256 threads / 8 warps x 16 q-rows, 2 CTAs/SM.
// smem: 2 bufs x {Kh,Kl,Vh,Vl} x 64x72 (73728 B) + Q hi/lo 128x72 (36864 B)
// = 110592 B.
// ---------------------------------------------------------------------------
__global__ __launch_bounds__(256, 2) void attn_kernel() {
    extern __shared__ __align__(16) __nv_bfloat16 sb[];
    const int t = threadIdx.x, lane = t & 31, warp = t >> 5;
    const int g = lane >> 2, c4 = lane & 3;
    const int bh = blockIdx.y;
    const int kh = blockIdx.z;
    const int qr0 = blockIdx.x * 128;
    const int qloc = warp * 16;
    const int unit = (bh * 32 + blockIdx.x) * KSPLIT + kh;
    const int kt0 = kh * NTL;
    const uint32_t smem_u32 = (uint32_t)__cvta_generic_to_shared(sb);
    const size_t bho = (size_t)bh * NS * DH;

    const uint32_t qh_u = smem_u32 + (8 * 4608) * 2;
    const uint32_t ql_u = qh_u + 128 * 72 * 2;

    // ldmatrix lane-dependent byte offsets (pitch 72 elems = 144 B)
    const uint32_t a_ln = (uint32_t)(((lane & 7) + ((lane >> 3) & 1) * 8) * 144 + (lane >> 4) * 16);
    const uint32_t b_ln = (uint32_t)(((lane >> 4) * 8 + (lane & 7)) * 144 + ((lane >> 3) & 1) * 16);

    const __nv_bfloat16* srcs[4] = { g_k_hi + bho, g_k_lo + bho, g_v_hi + bho, g_v_lo + bho };

    auto issue = [&](int buf, int kt) {
        const int k0 = kt * 64;
#pragma unroll
        for (int arr = 0; arr < 4; arr++)
#pragma unroll
            for (int i = 0; i < 2; i++) {
                int ch = t * 2 + i;              // 0..511
                int row = ch >> 3, seg = ch & 7;
                const void* src = srcs[arr] + (size_t)(k0 + row) * DH + seg * 8;
                uint32_t dst = smem_u32 + ((buf * 4 + arr) * 4608 + row * 72 + seg * 8) * 2;
                cpa16(dst, src);
            }
    };

    // prologue: Q tile + KV(kt0) as group 0
    {
#pragma unroll
        for (int i = 0; i < 4; i++) {
            int ch = t * 4 + i;                  // 0..1023
            int row = ch >> 3, seg = ch & 7;
            cpa16(qh_u + (row * 72 + seg * 8) * 2, g_q_hi + bho + (size_t)(qr0 + row) * DH + seg * 8);
            cpa16(ql_u + (row * 72 + seg * 8) * 2, g_q_lo + bho + (size_t)(qr0 + row) * DH + seg * 8);
        }
    }
    issue(0, kt0);
    cp_commit();

    float o[8][4];
#pragma unroll
    for (int i = 0; i < 8; i++)
#pragma unroll
        for (int e = 0; e < 4; e++) o[i][e] = 0.f;
    float l0p = 0.f, l1p = 0.f;

    for (int lkt = 0; lkt < NTL; ++lkt) {
        cp_wait0();                      // group issued last iter complete
        __syncthreads();                 // all warps done reading buf (lkt+1)&1

        const int bb = lkt & 1;
        const uint32_t kh_u = smem_u32 + ((bb * 4 + 0) * 4608) * 2;
        const uint32_t kl_u = smem_u32 + ((bb * 4 + 1) * 4608) * 2;
        const uint32_t vh_u = smem_u32 + ((bb * 4 + 2) * 4608) * 2;
        const uint32_t vl_u = smem_u32 + ((bb * 4 + 3) * 4608) * 2;

        // ---- S = Q K^T - MFIX (accumulators pre-loaded with -MFIX)
        float s[8][4];
#pragma unroll
        for (int i = 0; i < 8; i++)
#pragma unroll
            for (int e = 0; e < 4; e++) s[i][e] = -MFIX;

#pragma unroll
        for (int ks = 0; ks < 4; ++ks) {
            uint32_t ah[4], al[4];
            uint32_t aro = (uint32_t)(qloc * 144 + ks * 32) + a_ln;
            ldm4(ah, qh_u + aro);
            ldm4(al, ql_u + aro);
#pragma unroll
            for (int p = 0; p < 4; ++p) {
                uint32_t bro = (uint32_t)(p * 16 * 144 + ks * 32) + b_ln;
                uint32_t bhr[4], blr[4];
                ldm4(bhr, kh_u + bro);
                ldm4(blr, kl_u + bro);
                mma_bf16(s[2 * p],     ah[0], ah[1], ah[2], ah[3], bhr[0], bhr[1]);
                mma_bf16(s[2 * p],     ah[0], ah[1], ah[2], ah[3], blr[0], blr[1]);
                mma_bf16(s[2 * p],     al[0], al[1], al[2], al[3], bhr[0], bhr[1]);
                mma_bf16(s[2 * p + 1], ah[0], ah[1], ah[2], ah[3], bhr[2], bhr[3]);
                mma_bf16(s[2 * p + 1], ah[0], ah[1], ah[2], ah[3], blr[2], blr[3]);
                mma_bf16(s[2 * p + 1], al[0], al[1], al[2], al[3], bhr[2], bhr[3]);
            }
        }

        // ---- prefetch tile lkt+1 (after S issue; hazard covered by the
        //      barrier above -- PV(lkt-1) reads of this buf are long done)
        if (lkt + 1 < NTL) { issue((lkt + 1) & 1, kt0 + lkt + 1); cp_commit(); }

        // ---- phase a: MUFU/ALU burst -- all exp + l accumulate + splits
        uint32_t ph[16], pl[16];
#pragma unroll
        for (int tk = 0; tk < 4; ++tk) {
            float p00 = ex2f(s[2 * tk][0]);
            float p01 = ex2f(s[2 * tk][1]);
            float p02 = ex2f(s[2 * tk][2]);
            float p03 = ex2f(s[2 * tk][3]);
            float p10 = ex2f(s[2 * tk + 1][0]);
            float p11 = ex2f(s[2 * tk + 1][1]);
            float p12 = ex2f(s[2 * tk + 1][2]);
            float p13 = ex2f(s[2 * tk + 1][3]);
            l0p += p00 + p01 + p10 + p11;
            l1p += p02 + p03 + p12 + p13;
            split_pack(p00, p01, ph[tk * 4 + 0], pl[tk * 4 + 0]);
            split_pack(p02, p03, ph[tk * 4 + 1], pl[tk * 4 + 1]);
            split_pack(p10, p11, ph[tk * 4 + 2], pl[tk * 4 + 2]);
            split_pack(p12, p13, ph[tk * 4 + 3], pl[tk * 4 + 3]);
        }

        // ---- phase b: uninterrupted ldmatrix + mma burst (PV)
        {
            int jbase = (lane & 15);
            int coff = (lane >> 4) * 8;
#pragma unroll
            for (int tk = 0; tk < 4; ++tk) {
                int jrow = tk * 16 + jbase;
#pragma unroll
                for (int np = 0; np < 4; ++np) {
                    uint32_t vh[4], vl[4];
                    ldm4t(vh, vh_u + (jrow * 72 + np * 16 + coff) * 2);
                    ldm4t(vl, vl_u + (jrow * 72 + np * 16 + coff) * 2);
                    mma_bf16(o[np * 2],     ph[tk*4+0], ph[tk*4+1], ph[tk*4+2], ph[tk*4+3], vh[0], vh[1]);
                    mma_bf16(o[np * 2],     ph[tk*4+0], ph[tk*4+1], ph[tk*4+2], ph[tk*4+3], vl[0], vl[1]);
                    mma_bf16(o[np * 2],     pl[tk*4+0], pl[tk*4+1], pl[tk*4+2], pl[tk*4+3], vh[0], vh[1]);
                    mma_bf16(o[np * 2 + 1], ph[tk*4+0], ph[tk*4+1], ph[tk*4+2], ph[tk*4+3], vh[2], vh[3]);
                    mma_bf16(o[np * 2 + 1], ph[tk*4+0], ph[tk*4+1], ph[tk*4+2], ph[tk*4+3], vl[2], vl[3]);
                    mma_bf16(o[np * 2 + 1], pl[tk*4+0], pl[tk*4+1], pl[tk*4+2], pl[tk*4+3], vh[2], vh[3]);
                }
            }
        }
    }

    // one-time l reduction across the 4 lanes of each row quad
    l0p += __shfl_xor_sync(0xffffffffu, l0p, 1);
    l0p += __shfl_xor_sync(0xffffffffu, l0p, 2);
    l1p += __shfl_xor_sync(0xffffffffu, l1p, 1);
    l1p += __shfl_xor_sync(0xffffffffu, l1p, 2);

    // epilogue: write RAW fp32 partials (no normalization)
    {
        int r0 = qloc + g, r1 = qloc + g + 8;
        if (c4 == 0) {
            g_pl[(size_t)unit * 128 + r0] = l0p;
            g_pl[(size_t)unit * 128 + r1] = l1p;
        }
        float* base0 = g_po + ((size_t)unit * 128 + r0) * 64;
        float* base1 = g_po + ((size_t)unit * 128 + r1) * 64;
#pragma unroll
        for (int nt = 0; nt < 8; ++nt) {
            int d = nt * 8 + c4 * 2;
            *(float2*)&base0[d] = make_float2(o[nt][0], o[nt][1]);
            *(float2*)&base1[d] = make_float2(o[nt][2], o[nt][3]);
        }
    }
}

// ---------------------------------------------------------------------------
// Combine split-K partials: O = (sum O_k) / (sum l_k), then bf16 hi/lo split
// into g_a_hi/lo [s][dm]. Block per (qt, bh); 256 threads; thread = (row%4, col).
// ---------------------------------------------------------------------------
__global__ __launch_bounds__(256) void combine_kernel() {
    const int qt = blockIdx.x, bh = blockIdx.y;
    const int ua = (bh * 32 + qt) * KSPLIT;
    const int t = threadIdx.x;
    const int col = t & 63, rbase = t >> 6;      // 4 rows per pass
    const int b_ = bh >> 3, h_ = bh & 7;
#pragma unroll 4
    for (int i = 0; i < 32; i++) {
        int row = rbase + i * 4;
        float lsum = 0.f, osum = 0.f;
#pragma unroll
        for (int u = 0; u < KSPLIT; u++) {
            lsum += g_pl[(size_t)(ua + u) * 128 + row];
            osum += g_po[((size_t)(ua + u) * 128 + row) * 64 + col];
        }
        float v = osum / lsum;
        __nv_bfloat16 h, l;
        split1(v, h, l);
        size_t idx = ((size_t)(b_ * NS + qt * 128 + row)) * DM + h_ * 64 + col;
        g_a_hi[idx] = h;
        g_a_lo[idx] = l;
    }
}

// ---------------------------------------------------------------------------
extern "C" void kernel_launch(void* const* d_in, const int* in_sizes, int n_in,
                              void* d_out, int out_size) {
    const float* q  = (const float*)d_in[0];
    const float* k  = (const float*)d_in[1];
    const float* v  = (const float*)d_in[2];
    const float* wq = (const float*)d_in[3];
    const float* bq = (const float*)d_in[4];
    const float* wk = (const float*)d_in[5];
    const float* bk = (const float*)d_in[6];
    const float* wv = (const float*)d_in[7];
    const float* bv = (const float*)d_in[8];
    const float* wo = (const float*)d_in[9];
    const float* bo = (const float*)d_in[10];
    float* out = (float*)d_out;

    const int smem_gemm = 2 * 4 * 128 * 40 * 2;                  // 81920
    const int smem_attn = (8 * 4608 + 2 * 128 * 72) * 2;         // 110592
    cudaFuncSetAttribute(gemm_qkv_kernel, cudaFuncAttributeMaxDynamicSharedMemorySize, smem_gemm);
    cudaFuncSetAttribute(gemm_out_kernel, cudaFuncAttributeMaxDynamicSharedMemorySize, smem_gemm);
    cudaFuncSetAttribute(attn_kernel,     cudaFuncAttributeMaxDynamicSharedMemorySize, smem_attn);

    wsplit_kernel<<<dim3(16, 16, 4), dim3(32, 8)>>>(wq, wk, wv, wo);
    gemm_qkv_kernel<<<dim3(4, 64, 3), 256, smem_gemm>>>(q, k, v, bq, bk, bv);
    attn_kernel<<<dim3(32, 16, KSPLIT), 256, smem_attn>>>();
    combine_kernel<<<dim3(32, 16), 256>>>();
    gemm_out_kernel<<<dim3(4, 64), 256, smem_gemm>>>(bo, out);
}

// round 14
// speedup vs baseline: 1.1233x; 1.0104x over previous
#include <cuda_runtime.h>
#include <cuda_bf16.h>
#include <stdint.h>
#include <math.h>

#define NB 2
#define NS 4096
#define DM 512
#define NH 8
#define DH 64
#define MTOT (NB * NS)          // 8192
#define MK   (MTOT * DM)        // 4194304
#define NT   (NS / 64)          // 64
#define KSPLIT 4
#define NTL (NT / KSPLIT)       // 16 k-tiles per CTA
#define MFIX 12.0f              // fixed softmax max (log2 domain); scores bounded ~8

// ---------------------------------------------------------------------------
// Device-global scratch. bf16 hi/lo split pairs + fp32 split-K partials.
// ---------------------------------------------------------------------------
__device__ __align__(256) __nv_bfloat16 g_w_hi[4 * DM * DM], g_w_lo[4 * DM * DM]; // wT [z][n][k]
__device__ __align__(256) __nv_bfloat16 g_q_hi[MK], g_q_lo[MK];                   // [bh][s][dh], pre-scaled 0.125*log2e
__device__ __align__(256) __nv_bfloat16 g_k_hi[MK], g_k_lo[MK];                   // [bh][s][dh]
__device__ __align__(256) __nv_bfloat16 g_v_hi[MK], g_v_lo[MK];                   // [bh][s][dh]
__device__ __align__(256) float g_po[16 * 32 * KSPLIT * 128 * 64];                // [unit][row][col] raw O partials
__device__ __align__(256) float g_pl[16 * 32 * KSPLIT * 128];                     // [unit][row] raw l partials

// ---------------------------------------------------------------------------
// PTX helpers
// ---------------------------------------------------------------------------
__device__ __forceinline__ void mma_bf16(float* c, uint32_t a0, uint32_t a1,
                                         uint32_t a2, uint32_t a3,
                                         uint32_t b0, uint32_t b1) {
    asm volatile(
        "mma.sync.aligned.m16n8k16.row.col.f32.bf16.bf16.f32 "
        "{%0,%1,%2,%3},{%4,%5,%6,%7},{%8,%9},{%0,%1,%2,%3};"
        : "+f"(c[0]), "+f"(c[1]), "+f"(c[2]), "+f"(c[3])
        : "r"(a0), "r"(a1), "r"(a2), "r"(a3), "r"(b0), "r"(b1));
}

__device__ __forceinline__ void ldm4(uint32_t* r, uint32_t addr) {
    asm volatile(
        "ldmatrix.sync.aligned.m8n8.x4.shared.b16 {%0,%1,%2,%3},[%4];"
        : "=r"(r[0]), "=r"(r[1]), "=r"(r[2]), "=r"(r[3]) : "r"(addr));
}
__device__ __forceinline__ void ldm4t(uint32_t* r, uint32_t addr) {
    asm volatile(
        "ldmatrix.sync.aligned.m8n8.x4.trans.shared.b16 {%0,%1,%2,%3},[%4];"
        : "=r"(r[0]), "=r"(r[1]), "=r"(r[2]), "=r"(r[3]) : "r"(addr));
}

__device__ __forceinline__ void cpa16(uint32_t dst, const void* src) {
    asm volatile("cp.async.cg.shared.global [%0], [%1], 16;\n" :: "r"(dst), "l"(src));
}
__device__ __forceinline__ void cp_commit() { asm volatile("cp.async.commit_group;\n"); }
__device__ __forceinline__ void cp_wait0() { asm volatile("cp.async.wait_group 0;\n"); }

__device__ __forceinline__ float ex2f(float x) {
    float y;
    asm("ex2.approx.f32 %0, %1;" : "=f"(y) : "f"(x));
    return y;
}

// 2-term bf16 split of a float pair, packed: hi = {bf16(e1)|bf16(e0)},
// lo = residuals. cvt.rn.bf16x2 keeps identical rn rounding, 6 ops total.
__device__ __forceinline__ void split_pack(float e0, float e1, uint32_t& hi, uint32_t& lo) {
    uint32_t h;
    asm("cvt.rn.bf16x2.f32 %0, %1, %2;" : "=r"(h) : "f"(e1), "f"(e0));
    float f0 = __uint_as_float(h << 16);
    float f1 = __uint_as_float(h & 0xFFFF0000u);
    float r0 = e0 - f0;
    float r1 = e1 - f1;
    asm("cvt.rn.bf16x2.f32 %0, %1, %2;" : "=r"(lo) : "f"(r1), "f"(r0));
    hi = h;
}
__device__ __forceinline__ void split1(float x, __nv_bfloat16& h, __nv_bfloat16& l) {
    h = __float2bfloat16(x);
    l = __float2bfloat16(x - __bfloat162float(h));
}

// ---------------------------------------------------------------------------
// Weight transpose + split: w[k][n] fp32 -> wT_hi/lo[n][k] bf16
// ---------------------------------------------------------------------------
__global__ void wsplit_kernel(const float* __restrict__ wq, const float* __restrict__ wk,
                              const float* __restrict__ wv, const float* __restrict__ wo) {
    __shared__ float tl[32][33];
    const float* w = blockIdx.z == 0 ? wq : blockIdx.z == 1 ? wk : blockIdx.z == 2 ? wv : wo;
    const int n0 = blockIdx.x * 32, k0 = blockIdx.y * 32;
    const int tx = threadIdx.x, ty = threadIdx.y;  // 32 x 8
#pragma unroll
    for (int i = 0; i < 32; i += 8)
        tl[ty + i][tx] = w[(size_t)(k0 + ty + i) * DM + n0 + tx];
    __syncthreads();
#pragma unroll
    for (int i = 0; i < 32; i += 8) {
        float v = tl[tx][ty + i];
        __nv_bfloat16 h, l;
        split1(v, h, l);
        size_t idx = (size_t)blockIdx.z * DM * DM + (size_t)(n0 + ty + i) * DM + k0 + tx;
        g_w_hi[idx] = h;
        g_w_lo[idx] = l;
    }
}

// ---------------------------------------------------------------------------
// bf16 3-term GEMM core: C[128x128] block, 8 warps (2m x 4n), warp 64m x 32n.
// Fragments via ldmatrix.x4. Single barrier per k-iter.
// AMODE=1: A read as raw fp32 (LDG float4 -> split_pack -> STS), pipelined.
// AMODE=2: A assembled from KSPLIT split-K partials: sum, normalize by sum-l,
//          split -> STS. Deletes the separate combine pass entirely.
// ---------------------------------------------------------------------------
template <int AMODE>
__device__ __forceinline__ void gemm_core(const float* __restrict__ aF,
                                          const __nv_bfloat16* __restrict__ wH,
                                          const __nv_bfloat16* __restrict__ wL,
                                          const float* __restrict__ bias,
                                          int mode, int z, float* __restrict__ outF) {
    extern __shared__ __align__(16) __nv_bfloat16 sb[];
    const int t = threadIdx.x, lane = t & 31, warp = t >> 5;
    const int g = lane >> 2, c4 = lane & 3;
    const int wm = warp >> 2, wn = warp & 3;
    const int m0 = blockIdx.y * 128, n0 = blockIdx.x * 128;
    const uint32_t smem_u32 = (uint32_t)__cvta_generic_to_shared(sb);

    // ldmatrix lane-dependent byte offsets (pitch 40 elems = 80 B)
    const uint32_t a_ln = (uint32_t)(((lane & 7) + ((lane >> 3) & 1) * 8) * 80 + (lane >> 4) * 16);
    const uint32_t b_ln = (uint32_t)(((lane >> 4) * 8 + (lane & 7)) * 80 + ((lane >> 3) & 1) * 16);

    float c[4][4][4];
#pragma unroll
    for (int a = 0; a < 4; a++)
#pragma unroll
        for (int b = 0; b < 4; b++)
#pragma unroll
            for (int e = 0; e < 4; e++) c[a][b][e] = 0.f;

    // B (weights): always cp.async into arrays 2,3
    auto issueB = [&](int buf, int kc0) {
#pragma unroll
        for (int arr = 2; arr < 4; arr++)
#pragma unroll
            for (int i = 0; i < 2; i++) {
                int ch = t * 2 + i;
                int row = ch >> 2, seg = ch & 3;
                const __nv_bfloat16* base = (arr == 2) ? wH : wL;
                const void* src = base + (size_t)(n0 + row) * DM + kc0 + seg * 8;
                uint32_t dst = smem_u32 + ((buf * 4 + arr) * 5120 + row * 40 + seg * 8) * 2;
                cpa16(dst, src);
            }
    };

    // A staging registers (one 128x32 tile slice per thread = 8 fp32)
    float4 ar[4];

    auto ldgA = [&](int kc0) {
        if (AMODE == 1) {
#pragma unroll
            for (int i = 0; i < 2; i++) {
                int ch = t * 2 + i;
                int row = ch >> 2, seg = ch & 3;
                const float* p = aF + (size_t)(m0 + row) * DM + kc0 + seg * 8;
                ar[2 * i]     = *(const float4*)p;
                ar[2 * i + 1] = *(const float4*)(p + 4);
            }
        } else {  // AMODE == 2: combine split-K partials inline
#pragma unroll
            for (int i = 0; i < 2; i++) {
                int ch = t * 2 + i;
                int mrow = ch >> 2, seg = ch & 3;
                int m = m0 + mrow;
                int b_ = m >> 12, s_ = m & (NS - 1);
                int kc = kc0 + seg * 8;
                int h_ = kc >> 6, d_ = kc & 63;
                int ub = ((b_ * NH + h_) * 32 + (s_ >> 7)) * KSPLIT;
                int row = s_ & 127;
                const float* p = g_po + ((size_t)ub * 128 + row) * 64 + d_;
                float4 aa = make_float4(0.f, 0.f, 0.f, 0.f);
                float4 bb = make_float4(0.f, 0.f, 0.f, 0.f);
                float ls = 0.f;
#pragma unroll
                for (int u = 0; u < KSPLIT; u++) {
                    const float* pu = p + (size_t)u * (128 * 64);
                    float4 x0 = *(const float4*)pu;
                    float4 x1 = *(const float4*)(pu + 4);
                    aa.x += x0.x; aa.y += x0.y; aa.z += x0.z; aa.w += x0.w;
                    bb.x += x1.x; bb.y += x1.y; bb.z += x1.z; bb.w += x1.w;
                    ls += g_pl[(size_t)(ub + u) * 128 + row];
                }
                float inv = 1.0f / ls;
                ar[2 * i]     = make_float4(aa.x * inv, aa.y * inv, aa.z * inv, aa.w * inv);
                ar[2 * i + 1] = make_float4(bb.x * inv, bb.y * inv, bb.z * inv, bb.w * inv);
            }
        }
    };
    auto stsA = [&](int buf) {
#pragma unroll
        for (int i = 0; i < 2; i++) {
            int ch = t * 2 + i;
            int row = ch >> 2, seg = ch & 3;
            uint32_t h0, l0, h1, l1, h2, l2, h3, l3;
            split_pack(ar[2 * i].x, ar[2 * i].y, h0, l0);
            split_pack(ar[2 * i].z, ar[2 * i].w, h1, l1);
            split_pack(ar[2 * i + 1].x, ar[2 * i + 1].y, h2, l2);
            split_pack(ar[2 * i + 1].z, ar[2 * i + 1].w, h3, l3);
            uint32_t off_h = ((buf * 4 + 0) * 5120 + row * 40 + seg * 8) * 2;
            uint32_t off_l = ((buf * 4 + 1) * 5120 + row * 40 + seg * 8) * 2;
            *reinterpret_cast<uint4*>(reinterpret_cast<char*>(sb) + off_h) = make_uint4(h0, h1, h2, h3);
            *reinterpret_cast<uint4*>(reinterpret_cast<char*>(sb) + off_l) = make_uint4(l0, l1, l2, l3);
        }
    };

    ldgA(0);
    stsA(0);
    issueB(0, 0);
    cp_commit();
    ldgA(32);                            // stash A(1) in regs through iter 0

    for (int it = 0; it < 16; ++it) {
        cp_wait0();                      // group issued last iter complete
        __syncthreads();                 // all warps done with buf (it+1)&1
        if (it + 1 < 16) {
            stsA((it + 1) & 1);          // ar holds A(it+1); buf freed by barrier
            issueB((it + 1) & 1, (it + 1) * 32);
            cp_commit();
            if (it + 2 < 16) ldgA((it + 2) * 32);
        }

        const uint32_t Ah_u = smem_u32 + ((it & 1) * 4 + 0) * 5120 * 2;
        const uint32_t Al_u = smem_u32 + ((it & 1) * 4 + 1) * 5120 * 2;
        const uint32_t Bh_u = smem_u32 + ((it & 1) * 4 + 2) * 5120 * 2;
        const uint32_t Bl_u = smem_u32 + ((it & 1) * 4 + 3) * 5120 * 2;

#pragma unroll
        for (int ks = 0; ks < 2; ++ks) {
            uint32_t ah[4][4], al[4][4];
#pragma unroll
            for (int mt = 0; mt < 4; ++mt) {
                uint32_t ro = (uint32_t)((wm * 64 + mt * 16) * 80 + ks * 32) + a_ln;
                ldm4(ah[mt], Ah_u + ro);
                ldm4(al[mt], Al_u + ro);
            }
#pragma unroll
            for (int p = 0; p < 2; ++p) {
                uint32_t ro = (uint32_t)((wn * 32 + p * 16) * 80 + ks * 32) + b_ln;
                uint32_t bh[4], bl[4];
                ldm4(bh, Bh_u + ro);
                ldm4(bl, Bl_u + ro);
#pragma unroll
                for (int mt = 0; mt < 4; ++mt) {
                    mma_bf16(c[mt][2 * p], ah[mt][0], ah[mt][1], ah[mt][2], ah[mt][3], bh[0], bh[1]);
                    mma_bf16(c[mt][2 * p], ah[mt][0], ah[mt][1], ah[mt][2], ah[mt][3], bl[0], bl[1]);
                    mma_bf16(c[mt][2 * p], al[mt][0], al[mt][1], al[mt][2], al[mt][3], bh[0], bh[1]);
                    mma_bf16(c[mt][2 * p + 1], ah[mt][0], ah[mt][1], ah[mt][2], ah[mt][3], bh[2], bh[3]);
                    mma_bf16(c[mt][2 * p + 1], ah[mt][0], ah[mt][1], ah[mt][2], ah[mt][3], bl[2], bl[3]);
                    mma_bf16(c[mt][2 * p + 1], al[mt][0], al[mt][1], al[mt][2], al[mt][3], bh[2], bh[3]);
                }
            }
        }
    }

    // epilogue
    __nv_bfloat16* dh = z == 0 ? g_q_hi : z == 1 ? g_k_hi : g_v_hi;
    __nv_bfloat16* dl = z == 0 ? g_q_lo : z == 1 ? g_k_lo : g_v_lo;
    const float qscale = 0.125f * 1.44269504f;   // 1/sqrt(dh) * log2(e)
#pragma unroll
    for (int mt = 0; mt < 4; ++mt) {
        int mA = m0 + wm * 64 + mt * 16 + g;
#pragma unroll
        for (int nt = 0; nt < 4; ++nt) {
            int n = n0 + wn * 32 + nt * 8 + c4 * 2;
            float b0 = bias[n], b1 = bias[n + 1];
            float v00 = c[mt][nt][0] + b0, v01 = c[mt][nt][1] + b1;
            float v10 = c[mt][nt][2] + b0, v11 = c[mt][nt][3] + b1;
            if (mode == 0) {
                if (z == 0) { v00 *= qscale; v01 *= qscale; v10 *= qscale; v11 *= qscale; }
                int b_ = mA >> 12, s_ = mA & (NS - 1), h_ = n >> 6, d_ = n & 63;
                size_t idx = ((size_t)(b_ * NH + h_) * NS + s_) * DH + d_;
                uint32_t hi, lo;
                split_pack(v00, v01, hi, lo);
                *(uint32_t*)&dh[idx] = hi;
                *(uint32_t*)&dl[idx] = lo;
                split_pack(v10, v11, hi, lo);
                *(uint32_t*)&dh[idx + 8 * DH] = hi;
                *(uint32_t*)&dl[idx + 8 * DH] = lo;
            } else {
                outF[(size_t)mA * DM + n] = v00;
                outF[(size_t)mA * DM + n + 1] = v01;
                outF[(size_t)(mA + 8) * DM + n] = v10;
                outF[(size_t)(mA + 8) * DM + n + 1] = v11;
            }
        }
    }
}

__global__ __launch_bounds__(256, 2) void gemm_qkv_kernel(const float* __restrict__ q,
                                                          const float* __restrict__ k,
                                                          const float* __restrict__ v,
                                                          const float* __restrict__ bq,
                                                          const float* __restrict__ bk,
                                                          const float* __restrict__ bv) {
    const int z = blockIdx.z;
    const float* aF = z == 0 ? q : z == 1 ? k : v;
    const float* bias = z == 0 ? bq : z == 1 ? bk : bv;
    gemm_core<1>(aF,
                 g_w_hi + (size_t)z * DM * DM, g_w_lo + (size_t)z * DM * DM,
                 bias, 0, z, nullptr);
}

__global__ __launch_bounds__(256, 2) void gemm_out_kernel(const float* __restrict__ bo,
                                                          float* __restrict__ out) {
    gemm_core<2>(nullptr,
                 g_w_hi + (size_t)3 * DM * DM, g_w_lo + (size_t)3 * DM * DM,
                 bo, 1, 0, out);
}

// ---------------------------------------------------------------------------
// Flash attention (R11 config, best measured): bf16 3-term mma, FIXED-MAX
// softmax, SPLIT-K (KSPLIT=4), 256 threads / 8 warps x 16 q-rows, 2 CTAs/SM.
// smem: 2 bufs x {Kh,Kl,Vh,Vl} x 64x72 (73728 B) + Q hi/lo 128x72 (36864 B)
// = 110592 B.
// ---------------------------------------------------------------------------
__global__ __launch_bounds__(256, 2) void attn_kernel() {
    extern __shared__ __align__(16) __nv_bfloat16 sb[];
    const int t = threadIdx.x, lane = t & 31, warp = t >> 5;
    const int g = lane >> 2, c4 = lane & 3;
    const int bh = blockIdx.y;
    const int kh = blockIdx.z;
    const int qr0 = blockIdx.x * 128;
    const int qloc = warp * 16;
    const int unit = (bh * 32 + blockIdx.x) * KSPLIT + kh;
    const int kt0 = kh * NTL;
    const uint32_t smem_u32 = (uint32_t)__cvta_generic_to_shared(sb);
    const size_t bho = (size_t)bh * NS * DH;

    const uint32_t qh_u = smem_u32 + (8 * 4608) * 2;
    const uint32_t ql_u = qh_u + 128 * 72 * 2;

    // ldmatrix lane-dependent byte offsets (pitch 72 elems = 144 B)
    const uint32_t a_ln = (uint32_t)(((lane & 7) + ((lane >> 3) & 1) * 8) * 144 + (lane >> 4) * 16);
    const uint32_t b_ln = (uint32_t)(((lane >> 4) * 8 + (lane & 7)) * 144 + ((lane >> 3) & 1) * 16);

    const __nv_bfloat16* srcs[4] = { g_k_hi + bho, g_k_lo + bho, g_v_hi + bho, g_v_lo + bho };

    auto issue = [&](int buf, int kt) {
        const int k0 = kt * 64;
#pragma unroll
        for (int arr = 0; arr < 4; arr++)
#pragma unroll
            for (int i = 0; i < 2; i++) {
                int ch = t * 2 + i;              // 0..511
                int row = ch >> 3, seg = ch & 7;
                const void* src = srcs[arr] + (size_t)(k0 + row) * DH + seg * 8;
                uint32_t dst = smem_u32 + ((buf * 4 + arr) * 4608 + row * 72 + seg * 8) * 2;
                cpa16(dst, src);
            }
    };

    // prologue: Q tile + KV(kt0) as group 0
    {
#pragma unroll
        for (int i = 0; i < 4; i++) {
            int ch = t * 4 + i;                  // 0..1023
            int row = ch >> 3, seg = ch & 7;
            cpa16(qh_u + (row * 72 + seg * 8) * 2, g_q_hi + bho + (size_t)(qr0 + row) * DH + seg * 8);
            cpa16(ql_u + (row * 72 + seg * 8) * 2, g_q_lo + bho + (size_t)(qr0 + row) * DH + seg * 8);
        }
    }
    issue(0, kt0);
    cp_commit();

    float o[8][4];
#pragma unroll
    for (int i = 0; i < 8; i++)
#pragma unroll
        for (int e = 0; e < 4; e++) o[i][e] = 0.f;
    float l0p = 0.f, l1p = 0.f;

    for (int lkt = 0; lkt < NTL; ++lkt) {
        cp_wait0();                      // group issued last iter complete
        __syncthreads();                 // all warps done reading buf (lkt+1)&1

        const int bb = lkt & 1;
        const uint32_t kh_u = smem_u32 + ((bb * 4 + 0) * 4608) * 2;
        const uint32_t kl_u = smem_u32 + ((bb * 4 + 1) * 4608) * 2;
        const uint32_t vh_u = smem_u32 + ((bb * 4 + 2) * 4608) * 2;
        const uint32_t vl_u = smem_u32 + ((bb * 4 + 3) * 4608) * 2;

        // ---- S = Q K^T - MFIX (accumulators pre-loaded with -MFIX)
        float s[8][4];
#pragma unroll
        for (int i = 0; i < 8; i++)
#pragma unroll
            for (int e = 0; e < 4; e++) s[i][e] = -MFIX;

#pragma unroll
        for (int ks = 0; ks < 4; ++ks) {
            uint32_t ah[4], al[4];
            uint32_t aro = (uint32_t)(qloc * 144 + ks * 32) + a_ln;
            ldm4(ah, qh_u + aro);
            ldm4(al, ql_u + aro);
#pragma unroll
            for (int p = 0; p < 4; ++p) {
                uint32_t bro = (uint32_t)(p * 16 * 144 + ks * 32) + b_ln;
                uint32_t bhr[4], blr[4];
                ldm4(bhr, kh_u + bro);
                ldm4(blr, kl_u + bro);
                mma_bf16(s[2 * p],     ah[0], ah[1], ah[2], ah[3], bhr[0], bhr[1]);
                mma_bf16(s[2 * p],     ah[0], ah[1], ah[2], ah[3], blr[0], blr[1]);
                mma_bf16(s[2 * p],     al[0], al[1], al[2], al[3], bhr[0], bhr[1]);
                mma_bf16(s[2 * p + 1], ah[0], ah[1], ah[2], ah[3], bhr[2], bhr[3]);
                mma_bf16(s[2 * p + 1], ah[0], ah[1], ah[2], ah[3], blr[2], blr[3]);
                mma_bf16(s[2 * p + 1], al[0], al[1], al[2], al[3], bhr[2], bhr[3]);
            }
        }

        // ---- prefetch tile lkt+1 (after S issue; hazard covered by the
        //      barrier above -- PV(lkt-1) reads of this buf are long done)
        if (lkt + 1 < NTL) { issue((lkt + 1) & 1, kt0 + lkt + 1); cp_commit(); }

        // ---- phase a: MUFU/ALU burst -- all exp + l accumulate + splits
        uint32_t ph[16], pl[16];
#pragma unroll
        for (int tk = 0; tk < 4; ++tk) {
            float p00 = ex2f(s[2 * tk][0]);
            float p01 = ex2f(s[2 * tk][1]);
            float p02 = ex2f(s[2 * tk][2]);
            float p03 = ex2f(s[2 * tk][3]);
            float p10 = ex2f(s[2 * tk + 1][0]);
            float p11 = ex2f(s[2 * tk + 1][1]);
            float p12 = ex2f(s[2 * tk + 1][2]);
            float p13 = ex2f(s[2 * tk + 1][3]);
            l0p += p00 + p01 + p10 + p11;
            l1p += p02 + p03 + p12 + p13;
            split_pack(p00, p01, ph[tk * 4 + 0], pl[tk * 4 + 0]);
            split_pack(p02, p03, ph[tk * 4 + 1], pl[tk * 4 + 1]);
            split_pack(p10, p11, ph[tk * 4 + 2], pl[tk * 4 + 2]);
            split_pack(p12, p13, ph[tk * 4 + 3], pl[tk * 4 + 3]);
        }

        // ---- phase b: uninterrupted ldmatrix + mma burst (PV)
        {
            int jbase = (lane & 15);
            int coff = (lane >> 4) * 8;
#pragma unroll
            for (int tk = 0; tk < 4; ++tk) {
                int jrow = tk * 16 + jbase;
#pragma unroll
                for (int np = 0; np < 4; ++np) {
                    uint32_t vh[4], vl[4];
                    ldm4t(vh, vh_u + (jrow * 72 + np * 16 + coff) * 2);
                    ldm4t(vl, vl_u + (jrow * 72 + np * 16 + coff) * 2);
                    mma_bf16(o[np * 2],     ph[tk*4+0], ph[tk*4+1], ph[tk*4+2], ph[tk*4+3], vh[0], vh[1]);
                    mma_bf16(o[np * 2],     ph[tk*4+0], ph[tk*4+1], ph[tk*4+2], ph[tk*4+3], vl[0], vl[1]);
                    mma_bf16(o[np * 2],     pl[tk*4+0], pl[tk*4+1], pl[tk*4+2], pl[tk*4+3], vh[0], vh[1]);
                    mma_bf16(o[np * 2 + 1], ph[tk*4+0], ph[tk*4+1], ph[tk*4+2], ph[tk*4+3], vh[2], vh[3]);
                    mma_bf16(o[np * 2 + 1], ph[tk*4+0], ph[tk*4+1], ph[tk*4+2], ph[tk*4+3], vl[2], vl[3]);
                    mma_bf16(o[np * 2 + 1], pl[tk*4+0], pl[tk*4+1], pl[tk*4+2], pl[tk*4+3], vh[2], vh[3]);
                }
            }
        }
    }

    // one-time l reduction across the 4 lanes of each row quad
    l0p += __shfl_xor_sync(0xffffffffu, l0p, 1);
    l0p += __shfl_xor_sync(0xffffffffu, l0p, 2);
    l1p += __shfl_xor_sync(0xffffffffu, l1p, 1);
    l1p += __shfl_xor_sync(0xffffffffu, l1p, 2);

    // epilogue: write RAW fp32 partials (no normalization)
    {
        int r0 = qloc + g, r1 = qloc + g + 8;
        if (c4 == 0) {
            g_pl[(size_t)unit * 128 + r0] = l0p;
            g_pl[(size_t)unit * 128 + r1] = l1p;
        }
        float* base0 = g_po + ((size_t)unit * 128 + r0) * 64;
        float* base1 = g_po + ((size_t)unit * 128 + r1) * 64;
#pragma unroll
        for (int nt = 0; nt < 8; ++nt) {
            int d = nt * 8 + c4 * 2;
            *(float2*)&base0[d] = make_float2(o[nt][0], o[nt][1]);
            *(float2*)&base1[d] = make_float2(o[nt][2], o[nt][3]);
        }
    }
}

// ---------------------------------------------------------------------------
extern "C" void kernel_launch(void* const* d_in, const int* in_sizes, int n_in,
                              void* d_out, int out_size) {
    const float* q  = (const float*)d_in[0];
    const float* k  = (const float*)d_in[1];
    const float* v  = (const float*)d_in[2];
    const float* wq = (const float*)d_in[3];
    const float* bq = (const float*)d_in[4];
    const float* wk = (const float*)d_in[5];
    const float* bk = (const float*)d_in[6];
    const float* wv = (const float*)d_in[7];
    const float* bv = (const float*)d_in[8];
    const float* wo = (const float*)d_in[9];
    const float* bo = (const float*)d_in[10];
    float* out = (float*)d_out;

    const int smem_gemm = 2 * 4 * 128 * 40 * 2;                  // 81920
    const int smem_attn = (8 * 4608 + 2 * 128 * 72) * 2;         // 110592
    cudaFuncSetAttribute(gemm_qkv_kernel, cudaFuncAttributeMaxDynamicSharedMemorySize, smem_gemm);
    cudaFuncSetAttribute(gemm_out_kernel, cudaFuncAttributeMaxDynamicSharedMemorySize, smem_gemm);
    cudaFuncSetAttribute(attn_kernel,     cudaFuncAttributeMaxDynamicSharedMemorySize, smem_attn);

    wsplit_kernel<<<dim3(16, 16, 4), dim3(32, 8)>>>(wq, wk, wv, wo);
    gemm_qkv_kernel<<<dim3(4, 64, 3), 256, smem_gemm>>>(q, k, v, bq, bk, bv);
    attn_kernel<<<dim3(32, 16, KSPLIT), 256, smem_attn>>>();
    gemm_out_kernel<<<dim3(4, 64), 256, smem_gemm>>>(bo, out);
}

// round 15
// speedup vs baseline: 1.1264x; 1.0027x over previous
#include <cuda_runtime.h>
#include <cuda_bf16.h>
#include <stdint.h>
#include <math.h>

#define NB 2
#define NS 4096
#define DM 512
#define NH 8
#define DH 64
#define MTOT (NB * NS)          // 8192
#define MK   (MTOT * DM)        // 4194304
#define NT   (NS / 64)          // 64
#define KSPLIT 4
#define NTL (NT / KSPLIT)       // 16 k-tiles per CTA
#define MFIX 12.0f              // fixed softmax max (log2 domain); scores bounded ~8

// ---------------------------------------------------------------------------
// Device-global scratch. bf16 hi/lo split pairs + fp32 split-K partials.
// ---------------------------------------------------------------------------
__device__ __align__(256) __nv_bfloat16 g_w_hi[4 * DM * DM], g_w_lo[4 * DM * DM]; // wT [z][n][k]
__device__ __align__(256) __nv_bfloat16 g_q_hi[MK], g_q_lo[MK];                   // [bh][s][dh], pre-scaled 0.125*log2e
__device__ __align__(256) __nv_bfloat16 g_k_hi[MK], g_k_lo[MK];                   // [bh][s][dh]
__device__ __align__(256) __nv_bfloat16 g_v_hi[MK], g_v_lo[MK];                   // [bh][s][dh]
__device__ __align__(256) float g_po[16 * 32 * KSPLIT * 128 * 64];                // [unit][row][col] raw O partials
__device__ __align__(256) float g_pl[16 * 32 * KSPLIT * 128];                     // [unit][row] raw l partials

// ---------------------------------------------------------------------------
// PTX helpers
// ---------------------------------------------------------------------------
__device__ __forceinline__ void mma_bf16(float* c, uint32_t a0, uint32_t a1,
                                         uint32_t a2, uint32_t a3,
                                         uint32_t b0, uint32_t b1) {
    asm volatile(
        "mma.sync.aligned.m16n8k16.row.col.f32.bf16.bf16.f32 "
        "{%0,%1,%2,%3},{%4,%5,%6,%7},{%8,%9},{%0,%1,%2,%3};"
        : "+f"(c[0]), "+f"(c[1]), "+f"(c[2]), "+f"(c[3])
        : "r"(a0), "r"(a1), "r"(a2), "r"(a3), "r"(b0), "r"(b1));
}

__device__ __forceinline__ void ldm4(uint32_t* r, uint32_t addr) {
    asm volatile(
        "ldmatrix.sync.aligned.m8n8.x4.shared.b16 {%0,%1,%2,%3},[%4];"
        : "=r"(r[0]), "=r"(r[1]), "=r"(r[2]), "=r"(r[3]) : "r"(addr));
}
__device__ __forceinline__ void ldm4t(uint32_t* r, uint32_t addr) {
    asm volatile(
        "ldmatrix.sync.aligned.m8n8.x4.trans.shared.b16 {%0,%1,%2,%3},[%4];"
        : "=r"(r[0]), "=r"(r[1]), "=r"(r[2]), "=r"(r[3]) : "r"(addr));
}

__device__ __forceinline__ void cpa16(uint32_t dst, const void* src) {
    asm volatile("cp.async.cg.shared.global [%0], [%1], 16;\n" :: "r"(dst), "l"(src));
}
__device__ __forceinline__ void cp_commit() { asm volatile("cp.async.commit_group;\n"); }
__device__ __forceinline__ void cp_wait0() { asm volatile("cp.async.wait_group 0;\n"); }

__device__ __forceinline__ float ex2f(float x) {
    float y;
    asm("ex2.approx.f32 %0, %1;" : "=f"(y) : "f"(x));
    return y;
}

// 2-term bf16 split of a float pair, packed: hi = {bf16(e1)|bf16(e0)},
// lo = residuals. cvt.rn.bf16x2 keeps identical rn rounding, 6 ops total.
__device__ __forceinline__ void split_pack(float e0, float e1, uint32_t& hi, uint32_t& lo) {
    uint32_t h;
    asm("cvt.rn.bf16x2.f32 %0, %1, %2;" : "=r"(h) : "f"(e1), "f"(e0));
    float f0 = __uint_as_float(h << 16);
    float f1 = __uint_as_float(h & 0xFFFF0000u);
    float r0 = e0 - f0;
    float r1 = e1 - f1;
    asm("cvt.rn.bf16x2.f32 %0, %1, %2;" : "=r"(lo) : "f"(r1), "f"(r0));
    hi = h;
}
__device__ __forceinline__ void split1(float x, __nv_bfloat16& h, __nv_bfloat16& l) {
    h = __float2bfloat16(x);
    l = __float2bfloat16(x - __bfloat162float(h));
}

// ---------------------------------------------------------------------------
// Weight transpose + split: w[k][n] fp32 -> wT_hi/lo[n][k] bf16
// ---------------------------------------------------------------------------
__global__ void wsplit_kernel(const float* __restrict__ wq, const float* __restrict__ wk,
                              const float* __restrict__ wv, const float* __restrict__ wo) {
    __shared__ float tl[32][33];
    const float* w = blockIdx.z == 0 ? wq : blockIdx.z == 1 ? wk : blockIdx.z == 2 ? wv : wo;
    const int n0 = blockIdx.x * 32, k0 = blockIdx.y * 32;
    const int tx = threadIdx.x, ty = threadIdx.y;  // 32 x 8
#pragma unroll
    for (int i = 0; i < 32; i += 8)
        tl[ty + i][tx] = w[(size_t)(k0 + ty + i) * DM + n0 + tx];
    __syncthreads();
#pragma unroll
    for (int i = 0; i < 32; i += 8) {
        float v = tl[tx][ty + i];
        __nv_bfloat16 h, l;
        split1(v, h, l);
        size_t idx = (size_t)blockIdx.z * DM * DM + (size_t)(n0 + ty + i) * DM + k0 + tx;
        g_w_hi[idx] = h;
        g_w_lo[idx] = l;
    }
}

// ---------------------------------------------------------------------------
// bf16 3-term GEMM core: C[128x128] block, 8 warps (2m x 4n), warp 64m x 32n.
// Fragments via ldmatrix.x4. Single barrier per k-iter.
// AMODE=1: A read as raw fp32 (LDG float4 -> split_pack -> STS), pipelined.
// AMODE=2: A assembled from KSPLIT split-K partials: sum, normalize by a
//          PRECOMPUTED per-(head,row) 1/sum-l smem table (built once in the
//          prologue), split -> STS. No scalar gmem loads or rcp in the
//          steady-state dependency chain.
// ---------------------------------------------------------------------------
template <int AMODE>
__device__ __forceinline__ void gemm_core(const float* __restrict__ aF,
                                          const __nv_bfloat16* __restrict__ wH,
                                          const __nv_bfloat16* __restrict__ wL,
                                          const float* __restrict__ bias,
                                          int mode, int z, float* __restrict__ outF) {
    extern __shared__ __align__(16) __nv_bfloat16 sb[];
    const int t = threadIdx.x, lane = t & 31, warp = t >> 5;
    const int g = lane >> 2, c4 = lane & 3;
    const int wm = warp >> 2, wn = warp & 3;
    const int m0 = blockIdx.y * 128, n0 = blockIdx.x * 128;
    const uint32_t smem_u32 = (uint32_t)__cvta_generic_to_shared(sb);
    float* invl = reinterpret_cast<float*>(sb + 40960);   // after 81920 B of tiles

    // ldmatrix lane-dependent byte offsets (pitch 40 elems = 80 B)
    const uint32_t a_ln = (uint32_t)(((lane & 7) + ((lane >> 3) & 1) * 8) * 80 + (lane >> 4) * 16);
    const uint32_t b_ln = (uint32_t)(((lane >> 4) * 8 + (lane & 7)) * 80 + ((lane >> 3) & 1) * 16);

    float c[4][4][4];
#pragma unroll
    for (int a = 0; a < 4; a++)
#pragma unroll
        for (int b = 0; b < 4; b++)
#pragma unroll
            for (int e = 0; e < 4; e++) c[a][b][e] = 0.f;

    // ---- AMODE=2 prologue: per-(head,row) inverse-l table (1024 floats)
    if (AMODE == 2) {
#pragma unroll
        for (int e = t; e < NH * 128; e += 256) {
            int h_ = e >> 7, row = e & 127;
            int m = m0 + row;
            int b_ = m >> 12, s_ = m & (NS - 1);
            int ub = ((b_ * NH + h_) * 32 + (s_ >> 7)) * KSPLIT;
            int r = s_ & 127;
            float ls = 0.f;
#pragma unroll
            for (int u = 0; u < KSPLIT; u++)
                ls += g_pl[(size_t)(ub + u) * 128 + r];
            invl[e] = 1.0f / ls;
        }
        __syncthreads();
    }

    // B (weights): always cp.async into arrays 2,3
    auto issueB = [&](int buf, int kc0) {
#pragma unroll
        for (int arr = 2; arr < 4; arr++)
#pragma unroll
            for (int i = 0; i < 2; i++) {
                int ch = t * 2 + i;
                int row = ch >> 2, seg = ch & 3;
                const __nv_bfloat16* base = (arr == 2) ? wH : wL;
                const void* src = base + (size_t)(n0 + row) * DM + kc0 + seg * 8;
                uint32_t dst = smem_u32 + ((buf * 4 + arr) * 5120 + row * 40 + seg * 8) * 2;
                cpa16(dst, src);
            }
    };

    // A staging registers (one 128x32 tile slice per thread = 8 fp32)
    float4 ar[4];

    auto ldgA = [&](int kc0) {
        if (AMODE == 1) {
#pragma unroll
            for (int i = 0; i < 2; i++) {
                int ch = t * 2 + i;
                int row = ch >> 2, seg = ch & 3;
                const float* p = aF + (size_t)(m0 + row) * DM + kc0 + seg * 8;
                ar[2 * i]     = *(const float4*)p;
                ar[2 * i + 1] = *(const float4*)(p + 4);
            }
        } else {  // AMODE == 2: combine split-K partials inline
            const int h_ = kc0 >> 6;                     // constant across chunk
#pragma unroll
            for (int i = 0; i < 2; i++) {
                int ch = t * 2 + i;
                int mrow = ch >> 2, seg = ch & 3;
                int m = m0 + mrow;
                int b_ = m >> 12, s_ = m & (NS - 1);
                int kc = kc0 + seg * 8;
                int d_ = kc & 63;
                int ub = ((b_ * NH + h_) * 32 + (s_ >> 7)) * KSPLIT;
                int row = s_ & 127;
                const float* p = g_po + ((size_t)ub * 128 + row) * 64 + d_;
                float4 aa = make_float4(0.f, 0.f, 0.f, 0.f);
                float4 bb = make_float4(0.f, 0.f, 0.f, 0.f);
#pragma unroll
                for (int u = 0; u < KSPLIT; u++) {
                    const float* pu = p + (size_t)u * (128 * 64);
                    float4 x0 = *(const float4*)pu;
                    float4 x1 = *(const float4*)(pu + 4);
                    aa.x += x0.x; aa.y += x0.y; aa.z += x0.z; aa.w += x0.w;
                    bb.x += x1.x; bb.y += x1.y; bb.z += x1.z; bb.w += x1.w;
                }
                float inv = invl[h_ * 128 + mrow];
                ar[2 * i]     = make_float4(aa.x * inv, aa.y * inv, aa.z * inv, aa.w * inv);
                ar[2 * i + 1] = make_float4(bb.x * inv, bb.y * inv, bb.z * inv, bb.w * inv);
            }
        }
    };
    auto stsA = [&](int buf) {
#pragma unroll
        for (int i = 0; i < 2; i++) {
            int ch = t * 2 + i;
            int row = ch >> 2, seg = ch & 3;
            uint32_t h0, l0, h1, l1, h2, l2, h3, l3;
            split_pack(ar[2 * i].x, ar[2 * i].y, h0, l0);
            split_pack(ar[2 * i].z, ar[2 * i].w, h1, l1);
            split_pack(ar[2 * i + 1].x, ar[2 * i + 1].y, h2, l2);
            split_pack(ar[2 * i + 1].z, ar[2 * i + 1].w, h3, l3);
            uint32_t off_h = ((buf * 4 + 0) * 5120 + row * 40 + seg * 8) * 2;
            uint32_t off_l = ((buf * 4 + 1) * 5120 + row * 40 + seg * 8) * 2;
            *reinterpret_cast<uint4*>(reinterpret_cast<char*>(sb) + off_h) = make_uint4(h0, h1, h2, h3);
            *reinterpret_cast<uint4*>(reinterpret_cast<char*>(sb) + off_l) = make_uint4(l0, l1, l2, l3);
        }
    };

    ldgA(0);
    stsA(0);
    issueB(0, 0);
    cp_commit();
    ldgA(32);                            // stash A(1) in regs through iter 0

    for (int it = 0; it < 16; ++it) {
        cp_wait0();                      // group issued last iter complete
        __syncthreads();                 // all warps done with buf (it+1)&1
        if (it + 1 < 16) {
            stsA((it + 1) & 1);          // ar holds A(it+1); buf freed by barrier
            issueB((it + 1) & 1, (it + 1) * 32);
            cp_commit();
            if (it + 2 < 16) ldgA((it + 2) * 32);
        }

        const uint32_t Ah_u = smem_u32 + ((it & 1) * 4 + 0) * 5120 * 2;
        const uint32_t Al_u = smem_u32 + ((it & 1) * 4 + 1) * 5120 * 2;
        const uint32_t Bh_u = smem_u32 + ((it & 1) * 4 + 2) * 5120 * 2;
        const uint32_t Bl_u = smem_u32 + ((it & 1) * 4 + 3) * 5120 * 2;

#pragma unroll
        for (int ks = 0; ks < 2; ++ks) {
            uint32_t ah[4][4], al[4][4];
#pragma unroll
            for (int mt = 0; mt < 4; ++mt) {
                uint32_t ro = (uint32_t)((wm * 64 + mt * 16) * 80 + ks * 32) + a_ln;
                ldm4(ah[mt], Ah_u + ro);
                ldm4(al[mt], Al_u + ro);
            }
#pragma unroll
            for (int p = 0; p < 2; ++p) {
                uint32_t ro = (uint32_t)((wn * 32 + p * 16) * 80 + ks * 32) + b_ln;
                uint32_t bh[4], bl[4];
                ldm4(bh, Bh_u + ro);
                ldm4(bl, Bl_u + ro);
#pragma unroll
                for (int mt = 0; mt < 4; ++mt) {
                    mma_bf16(c[mt][2 * p], ah[mt][0], ah[mt][1], ah[mt][2], ah[mt][3], bh[0], bh[1]);
                    mma_bf16(c[mt][2 * p], ah[mt][0], ah[mt][1], ah[mt][2], ah[mt][3], bl[0], bl[1]);
                    mma_bf16(c[mt][2 * p], al[mt][0], al[mt][1], al[mt][2], al[mt][3], bh[0], bh[1]);
                    mma_bf16(c[mt][2 * p + 1], ah[mt][0], ah[mt][1], ah[mt][2], ah[mt][3], bh[2], bh[3]);
                    mma_bf16(c[mt][2 * p + 1], ah[mt][0], ah[mt][1], ah[mt][2], ah[mt][3], bl[2], bl[3]);
                    mma_bf16(c[mt][2 * p + 1], al[mt][0], al[mt][1], al[mt][2], al[mt][3], bh[2], bh[3]);
                }
            }
        }
    }

    // epilogue
    __nv_bfloat16* dh = z == 0 ? g_q_hi : z == 1 ? g_k_hi : g_v_hi;
    __nv_bfloat16* dl = z == 0 ? g_q_lo : z == 1 ? g_k_lo : g_v_lo;
    const float qscale = 0.125f * 1.44269504f;   // 1/sqrt(dh) * log2(e)
#pragma unroll
    for (int mt = 0; mt < 4; ++mt) {
        int mA = m0 + wm * 64 + mt * 16 + g;
#pragma unroll
        for (int nt = 0; nt < 4; ++nt) {
            int n = n0 + wn * 32 + nt * 8 + c4 * 2;
            float b0 = bias[n], b1 = bias[n + 1];
            float v00 = c[mt][nt][0] + b0, v01 = c[mt][nt][1] + b1;
            float v10 = c[mt][nt][2] + b0, v11 = c[mt][nt][3] + b1;
            if (mode == 0) {
                if (z == 0) { v00 *= qscale; v01 *= qscale; v10 *= qscale; v11 *= qscale; }
                int b_ = mA >> 12, s_ = mA & (NS - 1), h_ = n >> 6, d_ = n & 63;
                size_t idx = ((size_t)(b_ * NH + h_) * NS + s_) * DH + d_;
                uint32_t hi, lo;
                split_pack(v00, v01, hi, lo);
                *(uint32_t*)&dh[idx] = hi;
                *(uint32_t*)&dl[idx] = lo;
                split_pack(v10, v11, hi, lo);
                *(uint32_t*)&dh[idx + 8 * DH] = hi;
                *(uint32_t*)&dl[idx + 8 * DH] = lo;
            } else {
                outF[(size_t)mA * DM + n] = v00;
                outF[(size_t)mA * DM + n + 1] = v01;
                outF[(size_t)(mA + 8) * DM + n] = v10;
                outF[(size_t)(mA + 8) * DM + n + 1] = v11;
            }
        }
    }
}

__global__ __launch_bounds__(256, 2) void gemm_qkv_kernel(const float* __restrict__ q,
                                                          const float* __restrict__ k,
                                                          const float* __restrict__ v,
                                                          const float* __restrict__ bq,
                                                          const float* __restrict__ bk,
                                                          const float* __restrict__ bv) {
    const int z = blockIdx.z;
    const float* aF = z == 0 ? q : z == 1 ? k : v;
    const float* bias = z == 0 ? bq : z == 1 ? bk : bv;
    gemm_core<1>(aF,
                 g_w_hi + (size_t)z * DM * DM, g_w_lo + (size_t)z * DM * DM,
                 bias, 0, z, nullptr);
}

__global__ __launch_bounds__(256, 2) void gemm_out_kernel(const float* __restrict__ bo,
                                                          float* __restrict__ out) {
    gemm_core<2>(nullptr,
                 g_w_hi + (size_t)3 * DM * DM, g_w_lo + (size_t)3 * DM * DM,
                 bo, 1, 0, out);
}

// ---------------------------------------------------------------------------
// Flash attention (R11 config, best measured): bf16 3-term mma, FIXED-MAX
// softmax, SPLIT-K (KSPLIT=4), 256 threads / 8 warps x 16 q-rows, 2 CTAs/SM.
// smem: 2 bufs x {Kh,Kl,Vh,Vl} x 64x72 (73728 B) + Q hi/lo 128x72 (36864 B)
// = 110592 B.
// ---------------------------------------------------------------------------
__global__ __launch_bounds__(256, 2) void attn_kernel() {
    extern __shared__ __align__(16) __nv_bfloat16 sb[];
    const int t = threadIdx.x, lane = t & 31, warp = t >> 5;
    const int g = lane >> 2, c4 = lane & 3;
    const int bh = blockIdx.y;
    const int kh = blockIdx.z;
    const int qr0 = blockIdx.x * 128;
    const int qloc = warp * 16;
    const int unit = (bh * 32 + blockIdx.x) * KSPLIT + kh;
    const int kt0 = kh * NTL;
    const uint32_t smem_u32 = (uint32_t)__cvta_generic_to_shared(sb);
    const size_t bho = (size_t)bh * NS * DH;

    const uint32_t qh_u = smem_u32 + (8 * 4608) * 2;
    const uint32_t ql_u = qh_u + 128 * 72 * 2;

    // ldmatrix lane-dependent byte offsets (pitch 72 elems = 144 B)
    const uint32_t a_ln = (uint32_t)(((lane & 7) + ((lane >> 3) & 1) * 8) * 144 + (lane >> 4) * 16);
    const uint32_t b_ln = (uint32_t)(((lane >> 4) * 8 + (lane & 7)) * 144 + ((lane >> 3) & 1) * 16);

    const __nv_bfloat16* srcs[4] = { g_k_hi + bho, g_k_lo + bho, g_v_hi + bho, g_v_lo + bho };

    auto issue = [&](int buf, int kt) {
        const int k0 = kt * 64;
#pragma unroll
        for (int arr = 0; arr < 4; arr++)
#pragma unroll
            for (int i = 0; i < 2; i++) {
                int ch = t * 2 + i;              // 0..511
                int row = ch >> 3, seg = ch & 7;
                const void* src = srcs[arr] + (size_t)(k0 + row) * DH + seg * 8;
                uint32_t dst = smem_u32 + ((buf * 4 + arr) * 4608 + row * 72 + seg * 8) * 2;
                cpa16(dst, src);
            }
    };

    // prologue: Q tile + KV(kt0) as group 0
    {
#pragma unroll
        for (int i = 0; i < 4; i++) {
            int ch = t * 4 + i;                  // 0..1023
            int row = ch >> 3, seg = ch & 7;
            cpa16(qh_u + (row * 72 + seg * 8) * 2, g_q_hi + bho + (size_t)(qr0 + row) * DH + seg * 8);
            cpa16(ql_u + (row * 72 + seg * 8) * 2, g_q_lo + bho + (size_t)(qr0 + row) * DH + seg * 8);
        }
    }
    issue(0, kt0);
    cp_commit();

    float o[8][4];
#pragma unroll
    for (int i = 0; i < 8; i++)
#pragma unroll
        for (int e = 0; e < 4; e++) o[i][e] = 0.f;
    float l0p = 0.f, l1p = 0.f;

    for (int lkt = 0; lkt < NTL; ++lkt) {
        cp_wait0();                      // group issued last iter complete
        __syncthreads();                 // all warps done reading buf (lkt+1)&1

        const int bb = lkt & 1;
        const uint32_t kh_u = smem_u32 + ((bb * 4 + 0) * 4608) * 2;
        const uint32_t kl_u = smem_u32 + ((bb * 4 + 1) * 4608) * 2;
        const uint32_t vh_u = smem_u32 + ((bb * 4 + 2) * 4608) * 2;
        const uint32_t vl_u = smem_u32 + ((bb * 4 + 3) * 4608) * 2;

        // ---- S = Q K^T - MFIX (accumulators pre-loaded with -MFIX)
        float s[8][4];
#pragma unroll
        for (int i = 0; i < 8; i++)
#pragma unroll
            for (int e = 0; e < 4; e++) s[i][e] = -MFIX;

#pragma unroll
        for (int ks = 0; ks < 4; ++ks) {
            uint32_t ah[4], al[4];
            uint32_t aro = (uint32_t)(qloc * 144 + ks * 32) + a_ln;
            ldm4(ah, qh_u + aro);
            ldm4(al, ql_u + aro);
#pragma unroll
            for (int p = 0; p < 4; ++p) {
                uint32_t bro = (uint32_t)(p * 16 * 144 + ks * 32) + b_ln;
                uint32_t bhr[4], blr[4];
                ldm4(bhr, kh_u + bro);
                ldm4(blr, kl_u + bro);
                mma_bf16(s[2 * p],     ah[0], ah[1], ah[2], ah[3], bhr[0], bhr[1]);
                mma_bf16(s[2 * p],     ah[0], ah[1], ah[2], ah[3], blr[0], blr[1]);
                mma_bf16(s[2 * p],     al[0], al[1], al[2], al[3], bhr[0], bhr[1]);
                mma_bf16(s[2 * p + 1], ah[0], ah[1], ah[2], ah[3], bhr[2], bhr[3]);
                mma_bf16(s[2 * p + 1], ah[0], ah[1], ah[2], ah[3], blr[2], blr[3]);
                mma_bf16(s[2 * p + 1], al[0], al[1], al[2], al[3], bhr[2], bhr[3]);
            }
        }

        // ---- prefetch tile lkt+1 (after S issue; hazard covered by the
        //      barrier above -- PV(lkt-1) reads of this buf are long done)
        if (lkt + 1 < NTL) { issue((lkt + 1) & 1, kt0 + lkt + 1); cp_commit(); }

        // ---- phase a: MUFU/ALU burst -- all exp + l accumulate + splits
        uint32_t ph[16], pl[16];
#pragma unroll
        for (int tk = 0; tk < 4; ++tk) {
            float p00 = ex2f(s[2 * tk][0]);
            float p01 = ex2f(s[2 * tk][1]);
            float p02 = ex2f(s[2 * tk][2]);
            float p03 = ex2f(s[2 * tk][3]);
            float p10 = ex2f(s[2 * tk + 1][0]);
            float p11 = ex2f(s[2 * tk + 1][1]);
            float p12 = ex2f(s[2 * tk + 1][2]);
            float p13 = ex2f(s[2 * tk + 1][3]);
            l0p += p00 + p01 + p10 + p11;
            l1p += p02 + p03 + p12 + p13;
            split_pack(p00, p01, ph[tk * 4 + 0], pl[tk * 4 + 0]);
            split_pack(p02, p03, ph[tk * 4 + 1], pl[tk * 4 + 1]);
            split_pack(p10, p11, ph[tk * 4 + 2], pl[tk * 4 + 2]);
            split_pack(p12, p13, ph[tk * 4 + 3], pl[tk * 4 + 3]);
        }

        // ---- phase b: uninterrupted ldmatrix + mma burst (PV)
        {
            int jbase = (lane & 15);
            int coff = (lane >> 4) * 8;
#pragma unroll
            for (int tk = 0; tk < 4; ++tk) {
                int jrow = tk * 16 + jbase;
#pragma unroll
                for (int np = 0; np < 4; ++np) {
                    uint32_t vh[4], vl[4];
                    ldm4t(vh, vh_u + (jrow * 72 + np * 16 + coff) * 2);
                    ldm4t(vl, vl_u + (jrow * 72 + np * 16 + coff) * 2);
                    mma_bf16(o[np * 2],     ph[tk*4+0], ph[tk*4+1], ph[tk*4+2], ph[tk*4+3], vh[0], vh[1]);
                    mma_bf16(o[np * 2],     ph[tk*4+0], ph[tk*4+1], ph[tk*4+2], ph[tk*4+3], vl[0], vl[1]);
                    mma_bf16(o[np * 2],     pl[tk*4+0], pl[tk*4+1], pl[tk*4+2], pl[tk*4+3], vh[0], vh[1]);
                    mma_bf16(o[np * 2 + 1], ph[tk*4+0], ph[tk*4+1], ph[tk*4+2], ph[tk*4+3], vh[2], vh[3]);
                    mma_bf16(o[np * 2 + 1], ph[tk*4+0], ph[tk*4+1], ph[tk*4+2], ph[tk*4+3], vl[2], vl[3]);
                    mma_bf16(o[np * 2 + 1], pl[tk*4+0], pl[tk*4+1], pl[tk*4+2], pl[tk*4+3], vh[2], vh[3]);
                }
            }
        }
    }

    // one-time l reduction across the 4 lanes of each row quad
    l0p += __shfl_xor_sync(0xffffffffu, l0p, 1);
    l0p += __shfl_xor_sync(0xffffffffu, l0p, 2);
    l1p += __shfl_xor_sync(0xffffffffu, l1p, 1);
    l1p += __shfl_xor_sync(0xffffffffu, l1p, 2);

    // epilogue: write RAW fp32 partials (no normalization)
    {
        int r0 = qloc + g, r1 = qloc + g + 8;
        if (c4 == 0) {
            g_pl[(size_t)unit * 128 + r0] = l0p;
            g_pl[(size_t)unit * 128 + r1] = l1p;
        }
        float* base0 = g_po + ((size_t)unit * 128 + r0) * 64;
        float* base1 = g_po + ((size_t)unit * 128 + r1) * 64;
#pragma unroll
        for (int nt = 0; nt < 8; ++nt) {
            int d = nt * 8 + c4 * 2;
            *(float2*)&base0[d] = make_float2(o[nt][0], o[nt][1]);
            *(float2*)&base1[d] = make_float2(o[nt][2], o[nt][3]);
        }
    }
}

// ---------------------------------------------------------------------------
extern "C" void kernel_launch(void* const* d_in, const int* in_sizes, int n_in,
                              void* d_out, int out_size) {
    const float* q  = (const float*)d_in[0];
    const float* k  = (const float*)d_in[1];
    const float* v  = (const float*)d_in[2];
    const float* wq = (const float*)d_in[3];
    const float* bq = (const float*)d_in[4];
    const float* wk = (const float*)d_in[5];
    const float* bk = (const float*)d_in[6];
    const float* wv = (const float*)d_in[7];
    const float* bv = (const float*)d_in[8];
    const float* wo = (const float*)d_in[9];
    const float* bo = (const float*)d_in[10];
    float* out = (float*)d_out;

    const int smem_gemm = 2 * 4 * 128 * 40 * 2 + NH * 128 * 4;   // 81920 + 4096
    const int smem_attn = (8 * 4608 + 2 * 128 * 72) * 2;         // 110592
    cudaFuncSetAttribute(gemm_qkv_kernel, cudaFuncAttributeMaxDynamicSharedMemorySize, smem_gemm);
    cudaFuncSetAttribute(gemm_out_kernel, cudaFuncAttributeMaxDynamicSharedMemorySize, smem_gemm);
    cudaFuncSetAttribute(attn_kernel,     cudaFuncAttributeMaxDynamicSharedMemorySize, smem_attn);

    wsplit_kernel<<<dim3(16, 16, 4), dim3(32, 8)>>>(wq, wk, wv, wo);
    gemm_qkv_kernel<<<dim3(4, 64, 3), 256, smem_gemm>>>(q, k, v, bq, bk, bv);
    attn_kernel<<<dim3(32, 16, KSPLIT), 256, smem_attn>>>();
    gemm_out_kernel<<<dim3(4, 64), 256, smem_gemm>>>(bo, out);
}